// round 5
// baseline (speedup 1.0000x reference)
#include <cuda_runtime.h>
#include <math.h>

#define BB   2
#define LL   2048
#define SS   2048
#define DD   768
#define HH   12
#define HDIM 64
#define MTOT (BB*LL)   // 4096

// ---------------- scratch (no allocations allowed) ----------------
__device__ float g_Q [(size_t)BB*HH*LL*HDIM];   // (b,h,l,hd)
__device__ float g_K [(size_t)BB*HH*SS*HDIM];   // (b,h,s,hd)
__device__ float g_V [(size_t)BB*HH*HDIM*SS];   // (b,h,hd,s)  TRANSPOSED
__device__ float g_AO[(size_t)MTOT*DD];         // attention out, (b,l,d)
__device__ float g_X [(size_t)MTOT*DD];         // pre-LN residual

// ---------------- bf16 helpers ----------------
__device__ __forceinline__ unsigned bf2(float lo, float hi) {
    unsigned r; asm("cvt.rn.bf16x2.f32 %0, %1, %2;" : "=r"(r) : "f"(hi), "f"(lo));
    return r;
}
// interleave within 8-uint k-groups so (t, t+4) logical pairs are physically adjacent
__device__ __forceinline__ int icol(int u) {
    return (u & ~7) | (((u & 3) << 1) | ((u >> 2) & 1));
}
// D(16x8) += A(16x16) * B(16x8), bf16 in, f32 acc
__device__ __forceinline__ void mma16(float* c, unsigned a0, unsigned a1, unsigned a2, unsigned a3,
                                      unsigned b0, unsigned b1) {
    asm volatile(
        "mma.sync.aligned.m16n8k16.row.col.f32.bf16.bf16.f32 "
        "{%0,%1,%2,%3},{%4,%5,%6,%7},{%8,%9},{%0,%1,%2,%3};"
        : "+f"(c[0]), "+f"(c[1]), "+f"(c[2]), "+f"(c[3])
        : "r"(a0), "r"(a1), "r"(a2), "r"(a3), "r"(b0), "r"(b1));
}

#define GST 36   // smem row stride in uints (32 data + 4 pad -> bank = 4*row + col)

// =================== QKV projection GEMM (bf16 mma) ===================
// C[m,n] = sum_k A[m,k] * W[n,k]; BM=128, BN=64, BK=64; 256 thr (8 warps 4x2)
__global__ __launch_bounds__(256) void qkv_mma_kernel(
    const float* __restrict__ qin, const float* __restrict__ kin, const float* __restrict__ vin,
    const float* __restrict__ Wq,  const float* __restrict__ Wk,  const float* __restrict__ Wv)
{
    __shared__ unsigned As[128*GST];
    __shared__ unsigned Bs[64*GST];

    int which = blockIdx.z;
    const float* A  = (which == 0) ? qin : (which == 1) ? kin : vin;
    const float* Wt = (which == 0) ? Wq  : (which == 1) ? Wk  : Wv;
    float* Out      = (which == 0) ? g_Q : (which == 1) ? g_K : g_V;

    int tid = threadIdx.x, w = tid >> 5, lane = tid & 31;
    int g = lane >> 2, t = lane & 3;
    int wm = w & 3, wn = w >> 2;
    int m0 = blockIdx.x * 128, n0 = blockIdx.y * 64;

    int lr = tid >> 3, lc = tid & 7;
    const float* Ap = A  + (size_t)(m0 + lr) * DD + lc * 8;
    const float* Bp = Wt + (size_t)(n0 + lr) * DD + lc * 8;
    int ub = lc * 4;

    float c[2][4][4] = {};

    for (int k0 = 0; k0 < DD; k0 += 64) {
        #pragma unroll
        for (int i = 0; i < 4; i++) {
            const float* p = Ap + (size_t)i*32*DD + k0;
            float4 v0 = *(const float4*)p;
            float4 v1 = *(const float4*)(p + 4);
            unsigned* dst = As + (lr + i*32) * GST;
            dst[icol(ub  )] = bf2(v0.x, v0.y);
            dst[icol(ub+1)] = bf2(v0.z, v0.w);
            dst[icol(ub+2)] = bf2(v1.x, v1.y);
            dst[icol(ub+3)] = bf2(v1.z, v1.w);
        }
        #pragma unroll
        for (int i = 0; i < 2; i++) {
            const float* p = Bp + (size_t)i*32*DD + k0;
            float4 v0 = *(const float4*)p;
            float4 v1 = *(const float4*)(p + 4);
            unsigned* dst = Bs + (lr + i*32) * GST;
            dst[icol(ub  )] = bf2(v0.x, v0.y);
            dst[icol(ub+1)] = bf2(v0.z, v0.w);
            dst[icol(ub+2)] = bf2(v1.x, v1.y);
            dst[icol(ub+3)] = bf2(v1.z, v1.w);
        }
        __syncthreads();
        #pragma unroll
        for (int ks = 0; ks < 4; ks++) {
            int xc = ks*8 + 2*t;
            uint2 a01[2], a23[2];
            #pragma unroll
            for (int mt = 0; mt < 2; mt++) {
                int r = wm*32 + mt*16 + g;
                a01[mt] = *(const uint2*)(As + r*GST + xc);
                a23[mt] = *(const uint2*)(As + (r+8)*GST + xc);
            }
            uint2 bf[4];
            #pragma unroll
            for (int nt = 0; nt < 4; nt++)
                bf[nt] = *(const uint2*)(Bs + (wn*32 + nt*8 + g)*GST + xc);
            #pragma unroll
            for (int mt = 0; mt < 2; mt++)
                #pragma unroll
                for (int nt = 0; nt < 4; nt++)
                    mma16(c[mt][nt], a01[mt].x, a23[mt].x, a01[mt].y, a23[mt].y,
                          bf[nt].x, bf[nt].y);
        }
        __syncthreads();
    }

    // epilogue
    #pragma unroll
    for (int mt = 0; mt < 2; mt++) {
        #pragma unroll
        for (int nt = 0; nt < 4; nt++) {
            int m = m0 + wm*32 + mt*16 + g;
            int n = n0 + wn*32 + nt*8 + 2*t;
            int h = n >> 6, hd = n & 63;
            if (which < 2) {
                int bb = m >> 11, l = m & (LL-1);
                float* dst = Out + (((size_t)bb*HH + h)*LL + l)*HDIM + hd;
                *(float2*)dst = make_float2(c[mt][nt][0], c[mt][nt][1]);
                int m2 = m + 8; bb = m2 >> 11; l = m2 & (LL-1);
                dst = Out + (((size_t)bb*HH + h)*LL + l)*HDIM + hd;
                *(float2*)dst = make_float2(c[mt][nt][2], c[mt][nt][3]);
            } else {
                // V: (b,h,hd,s) transposed layout
                int bb = m >> 11, l = m & (LL-1);
                float* base = Out + (((size_t)bb*HH + h)*HDIM + hd)*SS + l;
                base[0]  = c[mt][nt][0];
                base[SS] = c[mt][nt][1];
                int m2 = m + 8; bb = m2 >> 11; l = m2 & (LL-1);
                base = Out + (((size_t)bb*HH + h)*HDIM + hd)*SS + l;
                base[0]  = c[mt][nt][2];
                base[SS] = c[mt][nt][3];
            }
        }
    }
}

// =================== flash attention (bf16 mma) ===================
// grid: (L/64, B*H), 128 threads (4 warps; warp w owns q-rows w*16..w*16+15)
__global__ __launch_bounds__(128) void attn_mma_kernel(const int* __restrict__ maskp)
{
    __shared__ unsigned Qs[64*GST];   // (q-row, d-pairs)   bf16x2
    __shared__ unsigned Ks[64*GST];   // (key,   d-pairs)
    __shared__ unsigned Vt[64*GST];   // (d,   key-pairs)   (gmem already d-major)
    __shared__ unsigned Ps[64*GST];   // (q-row, key-pairs)
    __shared__ float    mk[64];

    int tid = threadIdx.x, w = tid >> 5, lane = tid & 31;
    int g = lane >> 2, t = lane & 3;
    int bh = blockIdx.y;
    int b  = bh / HH, h = bh % HH;
    int q0 = blockIdx.x * 64;

    const float* Qg = g_Q + (size_t)bh * LL * HDIM;
    const float* Kg = g_K + (size_t)bh * SS * HDIM;
    const float* Vg = g_V + (size_t)bh * HDIM * SS;   // (hd, s)

    int lrow = tid & 63, half = tid >> 6;

    // load Q tile once
    {
        const float4* src = (const float4*)(Qg + (size_t)(q0 + lrow) * HDIM);
        #pragma unroll
        for (int i = 0; i < 8; i++) {
            int c4 = half*8 + i;
            float4 v = src[c4];
            Qs[lrow*GST + icol(2*c4  )] = bf2(v.x, v.y);
            Qs[lrow*GST + icol(2*c4+1)] = bf2(v.z, v.w);
        }
    }

    float o[8][4] = {};
    float mold0 = -1e30f, mold1 = -1e30f, l0 = 0.f, l1 = 0.f;

    const unsigned* qr0 = &Qs[(w*16 + g)*GST];
    const unsigned* qr1 = qr0 + 8*GST;
    unsigned* pr0 = &Ps[(w*16 + g)*GST];
    unsigned* pr1 = pr0 + 8*GST;

    for (int s0 = 0; s0 < SS; s0 += 64) {
        // load K (key-major) and V (d-major, contiguous keys)
        {
            const float4* ks = (const float4*)(Kg + (size_t)(s0 + lrow) * HDIM);
            const float4* vs = (const float4*)(Vg + (size_t)lrow * SS + s0);
            #pragma unroll
            for (int i = 0; i < 8; i++) {
                int c4 = half*8 + i;
                float4 kv = ks[c4];
                Ks[lrow*GST + icol(2*c4  )] = bf2(kv.x, kv.y);
                Ks[lrow*GST + icol(2*c4+1)] = bf2(kv.z, kv.w);
                float4 vv = vs[c4];
                Vt[lrow*GST + icol(2*c4  )] = bf2(vv.x, vv.y);
                Vt[lrow*GST + icol(2*c4+1)] = bf2(vv.z, vv.w);
            }
            if (tid < 64)
                mk[tid] = (1.0f - (float)maskp[(size_t)b*SS + s0 + tid]) * (-1000000.0f);
        }
        __syncthreads();

        // scores: S(16x64) = Q K^T
        float sc[8][4] = {};
        #pragma unroll
        for (int ks = 0; ks < 4; ks++) {
            int xc = ks*8 + 2*t;
            uint2 aA = *(const uint2*)(qr0 + xc);
            uint2 aB = *(const uint2*)(qr1 + xc);
            #pragma unroll
            for (int nt = 0; nt < 8; nt++) {
                uint2 bb2 = *(const uint2*)(Ks + (nt*8 + g)*GST + xc);
                mma16(sc[nt], aA.x, aB.x, aA.y, aB.y, bb2.x, bb2.y);
            }
        }

        // scale + mask + online softmax
        float mx0 = -1e30f, mx1 = -1e30f;
        #pragma unroll
        for (int nt = 0; nt < 8; nt++) {
            float2 mv = *(float2*)&mk[nt*8 + 2*t];
            sc[nt][0] = sc[nt][0]*0.125f + mv.x;
            sc[nt][1] = sc[nt][1]*0.125f + mv.y;
            sc[nt][2] = sc[nt][2]*0.125f + mv.x;
            sc[nt][3] = sc[nt][3]*0.125f + mv.y;
            mx0 = fmaxf(mx0, fmaxf(sc[nt][0], sc[nt][1]));
            mx1 = fmaxf(mx1, fmaxf(sc[nt][2], sc[nt][3]));
        }
        mx0 = fmaxf(mx0, __shfl_xor_sync(0xffffffffu, mx0, 1));
        mx0 = fmaxf(mx0, __shfl_xor_sync(0xffffffffu, mx0, 2));
        mx1 = fmaxf(mx1, __shfl_xor_sync(0xffffffffu, mx1, 1));
        mx1 = fmaxf(mx1, __shfl_xor_sync(0xffffffffu, mx1, 2));

        float mn0 = fmaxf(mold0, mx0), mn1 = fmaxf(mold1, mx1);
        float corr0 = __expf(mold0 - mn0), corr1 = __expf(mold1 - mn1);
        mold0 = mn0; mold1 = mn1;

        float sum0 = 0.f, sum1 = 0.f;
        #pragma unroll
        for (int nt = 0; nt < 8; nt++) {
            float p00 = __expf(sc[nt][0] - mn0), p01 = __expf(sc[nt][1] - mn0);
            float p10 = __expf(sc[nt][2] - mn1), p11 = __expf(sc[nt][3] - mn1);
            sum0 += p00 + p01; sum1 += p10 + p11;
            pr0[icol(nt*4 + t)] = bf2(p00, p01);
            pr1[icol(nt*4 + t)] = bf2(p10, p11);
        }
        sum0 += __shfl_xor_sync(0xffffffffu, sum0, 1);
        sum0 += __shfl_xor_sync(0xffffffffu, sum0, 2);
        sum1 += __shfl_xor_sync(0xffffffffu, sum1, 1);
        sum1 += __shfl_xor_sync(0xffffffffu, sum1, 2);
        l0 = l0*corr0 + sum0;
        l1 = l1*corr1 + sum1;
        #pragma unroll
        for (int nt = 0; nt < 8; nt++) {
            o[nt][0] *= corr0; o[nt][1] *= corr0;
            o[nt][2] *= corr1; o[nt][3] *= corr1;
        }
        __syncwarp();   // Ps rows are warp-private; order STS -> LDS

        // O += P(16x64) V(64x64)
        #pragma unroll
        for (int ks = 0; ks < 4; ks++) {
            int xc = ks*8 + 2*t;
            uint2 pA = *(const uint2*)(pr0 + xc);
            uint2 pB = *(const uint2*)(pr1 + xc);
            #pragma unroll
            for (int nt = 0; nt < 8; nt++) {
                uint2 bv = *(const uint2*)(Vt + (nt*8 + g)*GST + xc);
                mma16(o[nt], pA.x, pB.x, pA.y, pB.y, bv.x, bv.y);
            }
        }
        __syncthreads();   // before next tile overwrites Ks/Vt/mk
    }

    // epilogue: normalize, write merged-head layout (b,l,d)
    float inv0 = 1.0f / l0, inv1 = 1.0f / l1;
    int row0 = q0 + w*16 + g;
    float* dst0 = g_AO + ((size_t)b*LL + row0)*DD + h*HDIM;
    float* dst1 = dst0 + (size_t)8*DD;
    #pragma unroll
    for (int nt = 0; nt < 8; nt++) {
        *(float2*)&dst0[nt*8 + 2*t] = make_float2(o[nt][0]*inv0, o[nt][1]*inv0);
        *(float2*)&dst1[nt*8 + 2*t] = make_float2(o[nt][2]*inv1, o[nt][3]*inv1);
    }
}

// =================== output projection (bf16 mma) + bias + residual ===================
__global__ __launch_bounds__(256) void outproj_mma_kernel(
    const float* __restrict__ qin, const float* __restrict__ W,
    const float* __restrict__ bias)
{
    __shared__ unsigned As[128*GST];
    __shared__ unsigned Bs[64*GST];

    int tid = threadIdx.x, w = tid >> 5, lane = tid & 31;
    int g = lane >> 2, t = lane & 3;
    int wm = w & 3, wn = w >> 2;
    int m0 = blockIdx.x * 128, n0 = blockIdx.y * 64;

    int lr = tid >> 3, lc = tid & 7;
    const float* Ap = g_AO + (size_t)(m0 + lr) * DD + lc * 8;
    const float* Bp = W    + (size_t)(n0 + lr) * DD + lc * 8;
    int ub = lc * 4;

    float c[2][4][4] = {};

    for (int k0 = 0; k0 < DD; k0 += 64) {
        #pragma unroll
        for (int i = 0; i < 4; i++) {
            const float* p = Ap + (size_t)i*32*DD + k0;
            float4 v0 = *(const float4*)p;
            float4 v1 = *(const float4*)(p + 4);
            unsigned* dst = As + (lr + i*32) * GST;
            dst[icol(ub  )] = bf2(v0.x, v0.y);
            dst[icol(ub+1)] = bf2(v0.z, v0.w);
            dst[icol(ub+2)] = bf2(v1.x, v1.y);
            dst[icol(ub+3)] = bf2(v1.z, v1.w);
        }
        #pragma unroll
        for (int i = 0; i < 2; i++) {
            const float* p = Bp + (size_t)i*32*DD + k0;
            float4 v0 = *(const float4*)p;
            float4 v1 = *(const float4*)(p + 4);
            unsigned* dst = Bs + (lr + i*32) * GST;
            dst[icol(ub  )] = bf2(v0.x, v0.y);
            dst[icol(ub+1)] = bf2(v0.z, v0.w);
            dst[icol(ub+2)] = bf2(v1.x, v1.y);
            dst[icol(ub+3)] = bf2(v1.z, v1.w);
        }
        __syncthreads();
        #pragma unroll
        for (int ks = 0; ks < 4; ks++) {
            int xc = ks*8 + 2*t;
            uint2 a01[2], a23[2];
            #pragma unroll
            for (int mt = 0; mt < 2; mt++) {
                int r = wm*32 + mt*16 + g;
                a01[mt] = *(const uint2*)(As + r*GST + xc);
                a23[mt] = *(const uint2*)(As + (r+8)*GST + xc);
            }
            uint2 bf[4];
            #pragma unroll
            for (int nt = 0; nt < 4; nt++)
                bf[nt] = *(const uint2*)(Bs + (wn*32 + nt*8 + g)*GST + xc);
            #pragma unroll
            for (int mt = 0; mt < 2; mt++)
                #pragma unroll
                for (int nt = 0; nt < 4; nt++)
                    mma16(c[mt][nt], a01[mt].x, a23[mt].x, a01[mt].y, a23[mt].y,
                          bf[nt].x, bf[nt].y);
        }
        __syncthreads();
    }

    #pragma unroll
    for (int mt = 0; mt < 2; mt++) {
        #pragma unroll
        for (int nt = 0; nt < 4; nt++) {
            int m = m0 + wm*32 + mt*16 + g;
            int n = n0 + wn*32 + nt*8 + 2*t;
            float2 bi = *(const float2*)&bias[n];
            {
                float2 rs = *(const float2*)&qin[(size_t)m*DD + n];
                *(float2*)&g_X[(size_t)m*DD + n] =
                    make_float2(c[mt][nt][0] + bi.x + rs.x, c[mt][nt][1] + bi.y + rs.y);
            }
            {
                int m2 = m + 8;
                float2 rs = *(const float2*)&qin[(size_t)m2*DD + n];
                *(float2*)&g_X[(size_t)m2*DD + n] =
                    make_float2(c[mt][nt][2] + bi.x + rs.x, c[mt][nt][3] + bi.y + rs.y);
            }
        }
    }
}

// =================== LayerNorm ===================
__global__ __launch_bounds__(256) void ln_kernel(
    const float* __restrict__ gamma, const float* __restrict__ beta,
    float* __restrict__ out)
{
    __shared__ float sh[18];
    int row = blockIdx.x, tid = threadIdx.x;
    const float* x = g_X + (size_t)row * DD;
    float v0 = x[tid], v1 = x[tid+256], v2 = x[tid+512];
    float s  = v0 + v1 + v2;
    float sq = v0*v0 + v1*v1 + v2*v2;
    #pragma unroll
    for (int off = 16; off > 0; off >>= 1) {
        s  += __shfl_xor_sync(0xffffffffu, s,  off);
        sq += __shfl_xor_sync(0xffffffffu, sq, off);
    }
    int wid = tid >> 5;
    if ((tid & 31) == 0) { sh[wid] = s; sh[wid + 8] = sq; }
    __syncthreads();
    if (tid == 0) {
        float S = 0.f, Q2 = 0.f;
        #pragma unroll
        for (int i = 0; i < 8; i++) { S += sh[i]; Q2 += sh[i+8]; }
        float mu  = S  * (1.0f / 768.0f);
        float var = Q2 * (1.0f / 768.0f) - mu * mu;
        sh[16] = mu;
        sh[17] = rsqrtf(var + 1e-5f);
    }
    __syncthreads();
    float mu = sh[16], rstd = sh[17];
    float* o = out + (size_t)row * DD;
    o[tid]     = (v0 - mu) * rstd * gamma[tid]     + beta[tid];
    o[tid+256] = (v1 - mu) * rstd * gamma[tid+256] + beta[tid+256];
    o[tid+512] = (v2 - mu) * rstd * gamma[tid+512] + beta[tid+512];
}

// =================== launch ===================
extern "C" void kernel_launch(void* const* d_in, const int* in_sizes, int n_in,
                              void* d_out, int out_size)
{
    const float* q     = (const float*)d_in[0];
    const float* k     = (const float*)d_in[1];
    const float* v     = (const float*)d_in[2];
    const int*   mask  = (const int*)  d_in[3];
    const float* Wq    = (const float*)d_in[4];
    const float* Wk    = (const float*)d_in[5];
    const float* Wv    = (const float*)d_in[6];
    const float* W     = (const float*)d_in[7];
    const float* bias  = (const float*)d_in[8];
    const float* gamma = (const float*)d_in[9];
    const float* beta  = (const float*)d_in[10];
    float* out = (float*)d_out;

    qkv_mma_kernel    <<<dim3(MTOT/128, DD/64, 3), 256>>>(q, k, v, Wq, Wk, Wv);
    attn_mma_kernel   <<<dim3(LL/64, BB*HH), 128>>>(mask);
    outproj_mma_kernel<<<dim3(MTOT/128, DD/64), 256>>>(q, W, bias);
    ln_kernel         <<<MTOT, 256>>>(gamma, beta, out);
}

// round 7
// speedup vs baseline: 1.7385x; 1.7385x over previous
#include <cuda_runtime.h>
#include <math.h>

#define BB   2
#define LL   2048
#define SS   2048
#define DD   768
#define HH   12
#define HDIM 64
#define MTOT (BB*LL)   // 4096

// ---------------- scratch (no allocations allowed) ----------------
__device__ float g_Q [(size_t)BB*HH*LL*HDIM];   // (b,h,l,hd)
__device__ float g_K [(size_t)BB*HH*SS*HDIM];   // (b,h,s,hd)
__device__ float g_V [(size_t)BB*HH*SS*HDIM];   // (b,h,s,hd)  natural
__device__ float g_AO[(size_t)MTOT*DD];         // attention out, (b,l,d)
__device__ float g_X [(size_t)MTOT*DD];         // pre-LN residual

// ---------------- helpers ----------------
__device__ __forceinline__ unsigned bf2(float lo, float hi) {
    unsigned r; asm("cvt.rn.bf16x2.f32 %0, %1, %2;" : "=r"(r) : "f"(hi), "f"(lo));
    return r;
}
__device__ __forceinline__ void mma16(float* c, unsigned a0, unsigned a1, unsigned a2, unsigned a3,
                                      unsigned b0, unsigned b1) {
    asm volatile(
        "mma.sync.aligned.m16n8k16.row.col.f32.bf16.bf16.f32 "
        "{%0,%1,%2,%3},{%4,%5,%6,%7},{%8,%9},{%0,%1,%2,%3};"
        : "+f"(c[0]), "+f"(c[1]), "+f"(c[2]), "+f"(c[3])
        : "r"(a0), "r"(a1), "r"(a2), "r"(a3), "r"(b0), "r"(b1));
}
__device__ __forceinline__ void ldsm4(unsigned* r, unsigned a) {
    asm volatile("ldmatrix.sync.aligned.m8n8.x4.shared.b16 {%0,%1,%2,%3}, [%4];"
        : "=r"(r[0]), "=r"(r[1]), "=r"(r[2]), "=r"(r[3]) : "r"(a));
}
__device__ __forceinline__ void ldsm4t(unsigned* r, unsigned a) {
    asm volatile("ldmatrix.sync.aligned.m8n8.x4.trans.shared.b16 {%0,%1,%2,%3}, [%4];"
        : "=r"(r[0]), "=r"(r[1]), "=r"(r[2]), "=r"(r[3]) : "r"(a));
}
__device__ __forceinline__ unsigned saddr(const void* p) {
    return (unsigned)__cvta_generic_to_shared(p);
}
// tile: 128B rows (32 uints = 8 chunks of 16B), swizzle chunk ^= row&7
// store 8 consecutive bf16 (from 8 floats) at (row, chunk)
__device__ __forceinline__ void store8(unsigned* tile, int row, int chunk,
                                       float4 v0, float4 v1) {
    *(uint4*)(tile + row*32 + ((chunk ^ (row & 7)) << 2)) =
        make_uint4(bf2(v0.x, v0.y), bf2(v0.z, v0.w), bf2(v1.x, v1.y), bf2(v1.z, v1.w));
}

// =================== QKV projection GEMM (bf16 mma + ldmatrix) ===================
// C[m,n] = sum_k A[m,k] * W[n,k]; BM=128, BN=64, BK=64; 256 thr (8 warps 4x2)
__global__ __launch_bounds__(256) void qkv_mma_kernel(
    const float* __restrict__ qin, const float* __restrict__ kin, const float* __restrict__ vin,
    const float* __restrict__ Wq,  const float* __restrict__ Wk,  const float* __restrict__ Wv)
{
    __shared__ unsigned As[128*32];
    __shared__ unsigned Bs[64*32];

    int which = blockIdx.z;
    const float* A  = (which == 0) ? qin : (which == 1) ? kin : vin;
    const float* Wt = (which == 0) ? Wq  : (which == 1) ? Wk  : Wv;
    float* Out      = (which == 0) ? g_Q : (which == 1) ? g_K : g_V;

    int tid = threadIdx.x, w = tid >> 5, lane = tid & 31;
    int g = lane >> 2, t = lane & 3;
    int wm = w & 3, wn = w >> 2;
    int m0 = blockIdx.x * 128, n0 = blockIdx.y * 64;

    int lrA = tid >> 1, cbA = (tid & 1) * 4;
    int lrB = tid >> 2, cbB = (tid & 3) * 2;
    const float* Ap = A  + (size_t)(m0 + lrA) * DD;
    const float* Bp = Wt + (size_t)(n0 + lrB) * DD;

    int r7 = lane & 7;
    int rA = r7 + 8*((lane >> 3) & 1), cA = lane >> 4;   // A-frag lane row/chunk
    int rB = r7,                       cB = lane >> 3;   // B-frag lane row/chunk
    unsigned AsB = saddr(As), BsB = saddr(Bs);

    float acc[2][4][4] = {};

    for (int k0 = 0; k0 < DD; k0 += 64) {
        const float4* a4 = (const float4*)(Ap + k0);
        #pragma unroll
        for (int i = 0; i < 4; i++) { int c = cbA + i; store8(As, lrA, c, a4[2*c], a4[2*c+1]); }
        const float4* b4 = (const float4*)(Bp + k0);
        #pragma unroll
        for (int i = 0; i < 2; i++) { int c = cbB + i; store8(Bs, lrB, c, b4[2*c], b4[2*c+1]); }
        __syncthreads();

        #pragma unroll
        for (int jp = 0; jp < 2; jp++) {
            unsigned af[2][2][4];
            #pragma unroll
            for (int mt = 0; mt < 2; mt++)
                #pragma unroll
                for (int kk = 0; kk < 2; kk++) {
                    int r = wm*32 + mt*16 + rA;
                    int ch = 2*(2*jp + kk) + cA;
                    ldsm4(af[mt][kk], AsB + r*128 + ((ch ^ r7) << 4));
                }
            unsigned bf[4][4];
            #pragma unroll
            for (int nt = 0; nt < 4; nt++) {
                int r = wn*32 + nt*8 + rB;
                int ch = 4*jp + cB;
                ldsm4(bf[nt], BsB + r*128 + ((ch ^ r7) << 4));
            }
            #pragma unroll
            for (int mt = 0; mt < 2; mt++)
                #pragma unroll
                for (int nt = 0; nt < 4; nt++) {
                    mma16(acc[mt][nt], af[mt][0][0], af[mt][0][1], af[mt][0][2], af[mt][0][3],
                          bf[nt][0], bf[nt][1]);
                    mma16(acc[mt][nt], af[mt][1][0], af[mt][1][1], af[mt][1][2], af[mt][1][3],
                          bf[nt][2], bf[nt][3]);
                }
        }
        __syncthreads();
    }

    // epilogue: write (b,h,l,hd) layout (all three natural)
    #pragma unroll
    for (int mt = 0; mt < 2; mt++) {
        #pragma unroll
        for (int nt = 0; nt < 4; nt++) {
            int m = m0 + wm*32 + mt*16 + g;
            int n = n0 + wn*32 + nt*8 + 2*t;
            int h = n >> 6, hd = n & 63;
            int bb = m >> 11, l = m & (LL-1);
            *(float2*)(Out + (((size_t)bb*HH + h)*LL + l)*HDIM + hd) =
                make_float2(acc[mt][nt][0], acc[mt][nt][1]);
            int m2 = m + 8; bb = m2 >> 11; l = m2 & (LL-1);
            *(float2*)(Out + (((size_t)bb*HH + h)*LL + l)*HDIM + hd) =
                make_float2(acc[mt][nt][2], acc[mt][nt][3]);
        }
    }
}

// =================== flash attention (bf16 mma + ldmatrix, P in registers) ===================
// grid: (L/64, B*H), 128 threads (4 warps; warp w owns q-rows w*16..w*16+15)
__global__ __launch_bounds__(128) void attn_mma_kernel(const int* __restrict__ maskp)
{
    __shared__ unsigned Qs[64*32];
    __shared__ unsigned Ks[64*32];
    __shared__ unsigned Vs[64*32];
    __shared__ float    mk[64];

    int tid = threadIdx.x, w = tid >> 5, lane = tid & 31;
    int g = lane >> 2, t = lane & 3;
    int bh = blockIdx.y;
    int b  = bh / HH, h = bh % HH;
    int q0 = blockIdx.x * 64;

    const float* Qg = g_Q + (size_t)bh * LL * HDIM;
    const float* Kg = g_K + (size_t)bh * SS * HDIM;
    const float* Vg = g_V + (size_t)bh * SS * HDIM;

    int lrow = tid & 63, cb = (tid >> 6) * 4;
    int r7 = lane & 7;
    unsigned KsB = saddr(Ks), VsB = saddr(Vs), QsB = saddr(Qs);

    // load Q tile once
    {
        const float4* src = (const float4*)(Qg + (size_t)(q0 + lrow) * HDIM);
        #pragma unroll
        for (int i = 0; i < 4; i++) { int c = cb + i; store8(Qs, lrow, c, src[2*c], src[2*c+1]); }
    }
    __syncthreads();

    // Q fragments (resident in registers for whole kernel)
    unsigned qf[4][4];
    {
        int r = 16*w + r7 + 8*((lane >> 3) & 1);
        int cq = lane >> 4;
        #pragma unroll
        for (int kc = 0; kc < 4; kc++) {
            int ch = 2*kc + cq;
            ldsm4(qf[kc], QsB + r*128 + ((ch ^ r7) << 4));
        }
    }

    float o[8][4] = {};
    float mold0 = -1e30f, mold1 = -1e30f, l0 = 0.f, l1 = 0.f;

    int rK = r7,                       cK = lane >> 3;   // K b-frag
    int rV = r7 + 8*((lane >> 3) & 1), cV = lane >> 4;   // V trans b-frag

    for (int s0 = 0; s0 < SS; s0 += 64) {
        {
            const float4* ks = (const float4*)(Kg + (size_t)(s0 + lrow) * HDIM);
            const float4* vs = (const float4*)(Vg + (size_t)(s0 + lrow) * HDIM);
            #pragma unroll
            for (int i = 0; i < 4; i++) {
                int c = cb + i;
                store8(Ks, lrow, c, ks[2*c], ks[2*c+1]);
                store8(Vs, lrow, c, vs[2*c], vs[2*c+1]);
            }
            if (tid < 64)
                mk[tid] = (1.0f - (float)maskp[(size_t)b*SS + s0 + tid]) * (-1000000.0f);
        }
        __syncthreads();

        // scores S(16x64) = Q K^T
        float sc[8][4] = {};
        #pragma unroll
        for (int jp = 0; jp < 2; jp++) {
            #pragma unroll
            for (int nt = 0; nt < 8; nt++) {
                unsigned kb[4];
                int r = nt*8 + rK, ch = 4*jp + cK;
                ldsm4(kb, KsB + r*128 + ((ch ^ rK) << 4));
                mma16(sc[nt], qf[2*jp][0], qf[2*jp][1], qf[2*jp][2], qf[2*jp][3], kb[0], kb[1]);
                mma16(sc[nt], qf[2*jp+1][0], qf[2*jp+1][1], qf[2*jp+1][2], qf[2*jp+1][3], kb[2], kb[3]);
            }
        }

        // scale + mask + online softmax (rows g, g+8; 4 lanes/row)
        float mx0 = -1e30f, mx1 = -1e30f;
        #pragma unroll
        for (int nt = 0; nt < 8; nt++) {
            float2 mv = *(float2*)&mk[nt*8 + 2*t];
            sc[nt][0] = sc[nt][0]*0.125f + mv.x;
            sc[nt][1] = sc[nt][1]*0.125f + mv.y;
            sc[nt][2] = sc[nt][2]*0.125f + mv.x;
            sc[nt][3] = sc[nt][3]*0.125f + mv.y;
            mx0 = fmaxf(mx0, fmaxf(sc[nt][0], sc[nt][1]));
            mx1 = fmaxf(mx1, fmaxf(sc[nt][2], sc[nt][3]));
        }
        mx0 = fmaxf(mx0, __shfl_xor_sync(0xffffffffu, mx0, 1));
        mx0 = fmaxf(mx0, __shfl_xor_sync(0xffffffffu, mx0, 2));
        mx1 = fmaxf(mx1, __shfl_xor_sync(0xffffffffu, mx1, 1));
        mx1 = fmaxf(mx1, __shfl_xor_sync(0xffffffffu, mx1, 2));

        float mn0 = fmaxf(mold0, mx0), mn1 = fmaxf(mold1, mx1);
        float corr0 = __expf(mold0 - mn0), corr1 = __expf(mold1 - mn1);
        mold0 = mn0; mold1 = mn1;

        float sum0 = 0.f, sum1 = 0.f;
        #pragma unroll
        for (int nt = 0; nt < 8; nt++) {
            sc[nt][0] = __expf(sc[nt][0] - mn0);
            sc[nt][1] = __expf(sc[nt][1] - mn0);
            sc[nt][2] = __expf(sc[nt][2] - mn1);
            sc[nt][3] = __expf(sc[nt][3] - mn1);
            sum0 += sc[nt][0] + sc[nt][1];
            sum1 += sc[nt][2] + sc[nt][3];
        }
        sum0 += __shfl_xor_sync(0xffffffffu, sum0, 1);
        sum0 += __shfl_xor_sync(0xffffffffu, sum0, 2);
        sum1 += __shfl_xor_sync(0xffffffffu, sum1, 1);
        sum1 += __shfl_xor_sync(0xffffffffu, sum1, 2);
        l0 = l0*corr0 + sum0;
        l1 = l1*corr1 + sum1;
        #pragma unroll
        for (int nt = 0; nt < 8; nt++) {
            o[nt][0] *= corr0; o[nt][1] *= corr0;
            o[nt][2] *= corr1; o[nt][3] *= corr1;
        }

        // O += P(16x64) V(64x64); P packed straight from sc registers (C-frag == A-frag layout)
        #pragma unroll
        for (int j = 0; j < 4; j++) {
            unsigned a0 = bf2(sc[2*j][0],   sc[2*j][1]);
            unsigned a1 = bf2(sc[2*j][2],   sc[2*j][3]);
            unsigned a2 = bf2(sc[2*j+1][0], sc[2*j+1][1]);
            unsigned a3 = bf2(sc[2*j+1][2], sc[2*j+1][3]);
            #pragma unroll
            for (int np = 0; np < 4; np++) {
                unsigned vb[4];
                int r = 16*j + rV, ch = 2*np + cV;
                ldsm4t(vb, VsB + r*128 + ((ch ^ r7) << 4));
                mma16(o[2*np],   a0, a1, a2, a3, vb[0], vb[1]);
                mma16(o[2*np+1], a0, a1, a2, a3, vb[2], vb[3]);
            }
        }
        __syncthreads();   // before next tile overwrites Ks/Vs/mk
    }

    // epilogue: normalize, write merged-head layout (b,l,d)
    float inv0 = 1.0f / l0, inv1 = 1.0f / l1;
    int row0 = q0 + w*16 + g;
    float* dst0 = g_AO + ((size_t)b*LL + row0)*DD + h*HDIM;
    float* dst1 = dst0 + (size_t)8*DD;
    #pragma unroll
    for (int nt = 0; nt < 8; nt++) {
        *(float2*)&dst0[nt*8 + 2*t] = make_float2(o[nt][0]*inv0, o[nt][1]*inv0);
        *(float2*)&dst1[nt*8 + 2*t] = make_float2(o[nt][2]*inv1, o[nt][3]*inv1);
    }
}

// =================== output projection (bf16 mma + ldmatrix) + bias + residual ===================
__global__ __launch_bounds__(256) void outproj_mma_kernel(
    const float* __restrict__ qin, const float* __restrict__ W,
    const float* __restrict__ bias)
{
    __shared__ unsigned As[128*32];
    __shared__ unsigned Bs[64*32];

    int tid = threadIdx.x, w = tid >> 5, lane = tid & 31;
    int g = lane >> 2, t = lane & 3;
    int wm = w & 3, wn = w >> 2;
    int m0 = blockIdx.x * 128, n0 = blockIdx.y * 64;

    int lrA = tid >> 1, cbA = (tid & 1) * 4;
    int lrB = tid >> 2, cbB = (tid & 3) * 2;
    const float* Ap = g_AO + (size_t)(m0 + lrA) * DD;
    const float* Bp = W    + (size_t)(n0 + lrB) * DD;

    int r7 = lane & 7;
    int rA = r7 + 8*((lane >> 3) & 1), cA = lane >> 4;
    int rB = r7,                       cB = lane >> 3;
    unsigned AsB = saddr(As), BsB = saddr(Bs);

    float acc[2][4][4] = {};

    for (int k0 = 0; k0 < DD; k0 += 64) {
        const float4* a4 = (const float4*)(Ap + k0);
        #pragma unroll
        for (int i = 0; i < 4; i++) { int c = cbA + i; store8(As, lrA, c, a4[2*c], a4[2*c+1]); }
        const float4* b4 = (const float4*)(Bp + k0);
        #pragma unroll
        for (int i = 0; i < 2; i++) { int c = cbB + i; store8(Bs, lrB, c, b4[2*c], b4[2*c+1]); }
        __syncthreads();

        #pragma unroll
        for (int jp = 0; jp < 2; jp++) {
            unsigned af[2][2][4];
            #pragma unroll
            for (int mt = 0; mt < 2; mt++)
                #pragma unroll
                for (int kk = 0; kk < 2; kk++) {
                    int r = wm*32 + mt*16 + rA;
                    int ch = 2*(2*jp + kk) + cA;
                    ldsm4(af[mt][kk], AsB + r*128 + ((ch ^ r7) << 4));
                }
            unsigned bf[4][4];
            #pragma unroll
            for (int nt = 0; nt < 4; nt++) {
                int r = wn*32 + nt*8 + rB;
                int ch = 4*jp + cB;
                ldsm4(bf[nt], BsB + r*128 + ((ch ^ r7) << 4));
            }
            #pragma unroll
            for (int mt = 0; mt < 2; mt++)
                #pragma unroll
                for (int nt = 0; nt < 4; nt++) {
                    mma16(acc[mt][nt], af[mt][0][0], af[mt][0][1], af[mt][0][2], af[mt][0][3],
                          bf[nt][0], bf[nt][1]);
                    mma16(acc[mt][nt], af[mt][1][0], af[mt][1][1], af[mt][1][2], af[mt][1][3],
                          bf[nt][2], bf[nt][3]);
                }
        }
        __syncthreads();
    }

    #pragma unroll
    for (int mt = 0; mt < 2; mt++) {
        #pragma unroll
        for (int nt = 0; nt < 4; nt++) {
            int m = m0 + wm*32 + mt*16 + g;
            int n = n0 + wn*32 + nt*8 + 2*t;
            float2 bi = *(const float2*)&bias[n];
            {
                float2 rs = *(const float2*)&qin[(size_t)m*DD + n];
                *(float2*)&g_X[(size_t)m*DD + n] =
                    make_float2(acc[mt][nt][0] + bi.x + rs.x, acc[mt][nt][1] + bi.y + rs.y);
            }
            {
                int m2 = m + 8;
                float2 rs = *(const float2*)&qin[(size_t)m2*DD + n];
                *(float2*)&g_X[(size_t)m2*DD + n] =
                    make_float2(acc[mt][nt][2] + bi.x + rs.x, acc[mt][nt][3] + bi.y + rs.y);
            }
        }
    }
}

// =================== LayerNorm ===================
__global__ __launch_bounds__(256) void ln_kernel(
    const float* __restrict__ gamma, const float* __restrict__ beta,
    float* __restrict__ out)
{
    __shared__ float sh[18];
    int row = blockIdx.x, tid = threadIdx.x;
    const float* x = g_X + (size_t)row * DD;
    float v0 = x[tid], v1 = x[tid+256], v2 = x[tid+512];
    float s  = v0 + v1 + v2;
    float sq = v0*v0 + v1*v1 + v2*v2;
    #pragma unroll
    for (int off = 16; off > 0; off >>= 1) {
        s  += __shfl_xor_sync(0xffffffffu, s,  off);
        sq += __shfl_xor_sync(0xffffffffu, sq, off);
    }
    int wid = tid >> 5;
    if ((tid & 31) == 0) { sh[wid] = s; sh[wid + 8] = sq; }
    __syncthreads();
    if (tid == 0) {
        float S = 0.f, Q2 = 0.f;
        #pragma unroll
        for (int i = 0; i < 8; i++) { S += sh[i]; Q2 += sh[i+8]; }
        float mu  = S  * (1.0f / 768.0f);
        float var = Q2 * (1.0f / 768.0f) - mu * mu;
        sh[16] = mu;
        sh[17] = rsqrtf(var + 1e-5f);
    }
    __syncthreads();
    float mu = sh[16], rstd = sh[17];
    float* o = out + (size_t)row * DD;
    o[tid]     = (v0 - mu) * rstd * gamma[tid]     + beta[tid];
    o[tid+256] = (v1 - mu) * rstd * gamma[tid+256] + beta[tid+256];
    o[tid+512] = (v2 - mu) * rstd * gamma[tid+512] + beta[tid+512];
}

// =================== launch ===================
extern "C" void kernel_launch(void* const* d_in, const int* in_sizes, int n_in,
                              void* d_out, int out_size)
{
    const float* q     = (const float*)d_in[0];
    const float* k     = (const float*)d_in[1];
    const float* v     = (const float*)d_in[2];
    const int*   mask  = (const int*)  d_in[3];
    const float* Wq    = (const float*)d_in[4];
    const float* Wk    = (const float*)d_in[5];
    const float* Wv    = (const float*)d_in[6];
    const float* W     = (const float*)d_in[7];
    const float* bias  = (const float*)d_in[8];
    const float* gamma = (const float*)d_in[9];
    const float* beta  = (const float*)d_in[10];
    float* out = (float*)d_out;

    qkv_mma_kernel    <<<dim3(MTOT/128, DD/64, 3), 256>>>(q, k, v, Wq, Wk, Wv);
    attn_mma_kernel   <<<dim3(LL/64, BB*HH), 128>>>(mask);
    outproj_mma_kernel<<<dim3(MTOT/128, DD/64), 256>>>(q, W, bias);
    ln_kernel         <<<MTOT, 256>>>(gamma, beta, out);
}

// round 10
// speedup vs baseline: 2.8080x; 1.6152x over previous
#include <cuda_runtime.h>
#include <math.h>

#define BB   2
#define LL   2048
#define SS   2048
#define DD   768
#define HH   12
#define HDIM 64
#define MTOT (BB*LL)   // 4096

// ---------------- scratch (no allocations allowed) ----------------
// bf16 pairs stored as unsigned (bf16x2)
__device__ unsigned g_Qh [(size_t)BB*HH*LL*HDIM/2];   // (b,h,l,hd/2)
__device__ unsigned g_Kh [(size_t)BB*HH*SS*HDIM/2];
__device__ unsigned g_Vh [(size_t)BB*HH*SS*HDIM/2];
__device__ unsigned g_AOh[(size_t)MTOT*DD/2];         // attention out bf16, (b,l,d/2)
__device__ float    g_X  [(size_t)MTOT*DD];           // pre-LN residual fp32

// ---------------- helpers ----------------
__device__ __forceinline__ unsigned bf2(float lo, float hi) {
    unsigned r; asm("cvt.rn.bf16x2.f32 %0, %1, %2;" : "=r"(r) : "f"(hi), "f"(lo));
    return r;
}
__device__ __forceinline__ void mma16(float* c, unsigned a0, unsigned a1, unsigned a2, unsigned a3,
                                      unsigned b0, unsigned b1) {
    asm volatile(
        "mma.sync.aligned.m16n8k16.row.col.f32.bf16.bf16.f32 "
        "{%0,%1,%2,%3},{%4,%5,%6,%7},{%8,%9},{%0,%1,%2,%3};"
        : "+f"(c[0]), "+f"(c[1]), "+f"(c[2]), "+f"(c[3])
        : "r"(a0), "r"(a1), "r"(a2), "r"(a3), "r"(b0), "r"(b1));
}
__device__ __forceinline__ void ldsm4(unsigned* r, unsigned a) {
    asm volatile("ldmatrix.sync.aligned.m8n8.x4.shared.b16 {%0,%1,%2,%3}, [%4];"
        : "=r"(r[0]), "=r"(r[1]), "=r"(r[2]), "=r"(r[3]) : "r"(a));
}
__device__ __forceinline__ void ldsm4t(unsigned* r, unsigned a) {
    asm volatile("ldmatrix.sync.aligned.m8n8.x4.trans.shared.b16 {%0,%1,%2,%3}, [%4];"
        : "=r"(r[0]), "=r"(r[1]), "=r"(r[2]), "=r"(r[3]) : "r"(a));
}
__device__ __forceinline__ unsigned saddr(const void* p) {
    return (unsigned)__cvta_generic_to_shared(p);
}
__device__ __forceinline__ void cpa16(unsigned sdst, const void* gsrc) {
    asm volatile("cp.async.cg.shared.global [%0], [%1], 16;" :: "r"(sdst), "l"(gsrc));
}
// tile: 128B rows (32 uints = 8 chunks of 16B), swizzle chunk ^= row&7
__device__ __forceinline__ void store8(unsigned* tile, int row, int chunk,
                                       float4 v0, float4 v1) {
    *(uint4*)(tile + row*32 + ((chunk ^ (row & 7)) << 2)) =
        make_uint4(bf2(v0.x, v0.y), bf2(v0.z, v0.w), bf2(v1.x, v1.y), bf2(v1.z, v1.w));
}

// =================== QKV projection GEMM (bf16 mma + ldmatrix) ===================
// C[m,n] = sum_k A[m,k] * W[n,k]; BM=128, BN=64, BK=64; 256 thr (8 warps 4x2)
// writes bf16 scratch
__global__ __launch_bounds__(256) void qkv_mma_kernel(
    const float* __restrict__ qin, const float* __restrict__ kin, const float* __restrict__ vin,
    const float* __restrict__ Wq,  const float* __restrict__ Wk,  const float* __restrict__ Wv)
{
    __shared__ unsigned As[128*32];
    __shared__ unsigned Bs[64*32];

    int which = blockIdx.z;
    const float* A  = (which == 0) ? qin : (which == 1) ? kin : vin;
    const float* Wt = (which == 0) ? Wq  : (which == 1) ? Wk  : Wv;
    unsigned* Out   = (which == 0) ? g_Qh : (which == 1) ? g_Kh : g_Vh;

    int tid = threadIdx.x, w = tid >> 5, lane = tid & 31;
    int g = lane >> 2, t = lane & 3;
    int wm = w & 3, wn = w >> 2;
    int m0 = blockIdx.x * 128, n0 = blockIdx.y * 64;

    int lrA = tid >> 1, cbA = (tid & 1) * 4;
    int lrB = tid >> 2, cbB = (tid & 3) * 2;
    const float* Ap = A  + (size_t)(m0 + lrA) * DD;
    const float* Bp = Wt + (size_t)(n0 + lrB) * DD;

    int r7 = lane & 7;
    int rA = r7 + 8*((lane >> 3) & 1), cA = lane >> 4;
    int rB = r7,                       cB = lane >> 3;
    unsigned AsB = saddr(As), BsB = saddr(Bs);

    float acc[2][4][4] = {};

    for (int k0 = 0; k0 < DD; k0 += 64) {
        const float4* a4 = (const float4*)(Ap + k0);
        #pragma unroll
        for (int i = 0; i < 4; i++) { int c = cbA + i; store8(As, lrA, c, a4[2*c], a4[2*c+1]); }
        const float4* b4 = (const float4*)(Bp + k0);
        #pragma unroll
        for (int i = 0; i < 2; i++) { int c = cbB + i; store8(Bs, lrB, c, b4[2*c], b4[2*c+1]); }
        __syncthreads();

        #pragma unroll
        for (int jp = 0; jp < 2; jp++) {
            unsigned af[2][2][4];
            #pragma unroll
            for (int mt = 0; mt < 2; mt++)
                #pragma unroll
                for (int kk = 0; kk < 2; kk++) {
                    int r = wm*32 + mt*16 + rA;
                    int ch = 2*(2*jp + kk) + cA;
                    ldsm4(af[mt][kk], AsB + r*128 + ((ch ^ r7) << 4));
                }
            unsigned bf[4][4];
            #pragma unroll
            for (int nt = 0; nt < 4; nt++) {
                int r = wn*32 + nt*8 + rB;
                int ch = 4*jp + cB;
                ldsm4(bf[nt], BsB + r*128 + ((ch ^ r7) << 4));
            }
            #pragma unroll
            for (int mt = 0; mt < 2; mt++)
                #pragma unroll
                for (int nt = 0; nt < 4; nt++) {
                    mma16(acc[mt][nt], af[mt][0][0], af[mt][0][1], af[mt][0][2], af[mt][0][3],
                          bf[nt][0], bf[nt][1]);
                    mma16(acc[mt][nt], af[mt][1][0], af[mt][1][1], af[mt][1][2], af[mt][1][3],
                          bf[nt][2], bf[nt][3]);
                }
        }
        __syncthreads();
    }

    // epilogue: bf16 pairs, (b,h,l,hd/2)
    #pragma unroll
    for (int mt = 0; mt < 2; mt++) {
        #pragma unroll
        for (int nt = 0; nt < 4; nt++) {
            int m = m0 + wm*32 + mt*16 + g;
            int n = n0 + wn*32 + nt*8 + 2*t;
            int h = n >> 6, hp = (n & 63) >> 1;
            int bb = m >> 11, l = m & (LL-1);
            Out[(((size_t)bb*HH + h)*LL + l)*32 + hp] = bf2(acc[mt][nt][0], acc[mt][nt][1]);
            int m2 = m + 8; bb = m2 >> 11; l = m2 & (LL-1);
            Out[(((size_t)bb*HH + h)*LL + l)*32 + hp] = bf2(acc[mt][nt][2], acc[mt][nt][3]);
        }
    }
}

// =================== flash attention: bf16, cp.async double-buffered ===================
// grid: (L/128, B*H), 256 threads (8 warps; warp w owns q-rows w*16..w*16+15)
// dyn smem: Qs[128*32] | KV[2][2][64*32] | mask[2][64]
#define ATTN_SMEM ((128*32 + 2*2*64*32) * 4 + 2*64*4)

__global__ __launch_bounds__(256) void attn_mma_kernel(const int* __restrict__ maskp)
{
    extern __shared__ unsigned dyn[];
    unsigned* Qs = dyn;                 // 128*32
    unsigned* KV = Qs + 128*32;         // [stage][K|V][64*32]
    int* mks     = (int*)(KV + 2*2*64*32);  // [stage][64]

    int tid = threadIdx.x, w = tid >> 5, lane = tid & 31;
    int g = lane >> 2, t = lane & 3;
    int bh = blockIdx.y;
    int b  = bh / HH, h = bh % HH;
    int q0 = blockIdx.x * 128;

    const unsigned* Qg = g_Qh + (size_t)bh * LL * 32;
    const unsigned* Kg = g_Kh + (size_t)bh * SS * 32;
    const unsigned* Vg = g_Vh + (size_t)bh * SS * 32;

    int r7 = lane & 7;
    unsigned QsB = saddr(Qs), KVB = saddr(KV), mkB = saddr(mks);

    // --- prefetch helper state ---
    int prow = tid >> 2;            // 0..63
    int pcb  = (tid & 3) * 2;       // chunk base {0,2,4,6}
    unsigned kdstB = KVB + prow*128 + (((pcb    ) ^ (prow & 7)) << 4);
    unsigned kdstB2= KVB + prow*128 + (((pcb + 1) ^ (prow & 7)) << 4);

    // load Q tile (plain copy, once)
    {
        int qrow = tid >> 1, qcb = (tid & 1) * 4;
        const uint4* src = (const uint4*)(Qg + (size_t)(q0 + qrow) * 32);
        #pragma unroll
        for (int i = 0; i < 4; i++) {
            int c = qcb + i;
            *(uint4*)(Qs + qrow*32 + ((c ^ (qrow & 7)) << 2)) = src[c];
        }
    }

    // prefetch KV tile 0 into stage 0
    {
        const uint4* kg = (const uint4*)(Kg + (size_t)prow * 32);
        const uint4* vg = (const uint4*)(Vg + (size_t)prow * 32);
        cpa16(kdstB,          kg + pcb);
        cpa16(kdstB2,         kg + pcb + 1);
        cpa16(kdstB  + 8192,  vg + pcb);
        cpa16(kdstB2 + 8192,  vg + pcb + 1);
        if (tid < 16) cpa16(mkB + tid*16, maskp + (size_t)b*SS + tid*4);
        asm volatile("cp.async.commit_group;");
    }
    __syncthreads();

    // Q fragments (resident)
    unsigned qf[4][4];
    {
        int r = 16*w + r7 + 8*((lane >> 3) & 1);
        int cq = lane >> 4;
        #pragma unroll
        for (int kc = 0; kc < 4; kc++) {
            int ch = 2*kc + cq;
            ldsm4(qf[kc], QsB + r*128 + ((ch ^ r7) << 4));
        }
    }

    float o[8][4] = {};
    float mold0 = -1e30f, mold1 = -1e30f, l0 = 0.f, l1 = 0.f;

    int rK = r7,                       cK = lane >> 3;   // K b-frag
    int rV = r7 + 8*((lane >> 3) & 1), cV = lane >> 4;   // V trans b-frag

    const int NT = SS / 64;
    for (int it = 0; it < NT; it++) {
        int st = it & 1;
        // prefetch next tile into other stage
        if (it + 1 < NT) {
            int s0n = (it + 1) * 64;
            int stn = st ^ 1;
            const uint4* kg = (const uint4*)(Kg + (size_t)(s0n + prow) * 32);
            const uint4* vg = (const uint4*)(Vg + (size_t)(s0n + prow) * 32);
            unsigned off = stn * 16384;
            cpa16(kdstB  + off,        kg + pcb);
            cpa16(kdstB2 + off,        kg + pcb + 1);
            cpa16(kdstB  + off + 8192, vg + pcb);
            cpa16(kdstB2 + off + 8192, vg + pcb + 1);
            if (tid < 16) cpa16(mkB + stn*256 + tid*16, maskp + (size_t)b*SS + s0n + tid*4);
            asm volatile("cp.async.commit_group;");
            asm volatile("cp.async.wait_group 1;");
        } else {
            asm volatile("cp.async.wait_group 0;");
        }
        __syncthreads();

        unsigned KsB = KVB + st*16384;
        unsigned VsB = KsB + 8192;
        const int* mkp = mks + st*64;

        // scores S(16x64) = Q K^T
        float sc[8][4] = {};
        #pragma unroll
        for (int jp = 0; jp < 2; jp++) {
            #pragma unroll
            for (int nt = 0; nt < 8; nt++) {
                unsigned kb[4];
                int r = nt*8 + rK, ch = 4*jp + cK;
                ldsm4(kb, KsB + r*128 + ((ch ^ rK) << 4));
                mma16(sc[nt], qf[2*jp][0], qf[2*jp][1], qf[2*jp][2], qf[2*jp][3], kb[0], kb[1]);
                mma16(sc[nt], qf[2*jp+1][0], qf[2*jp+1][1], qf[2*jp+1][2], qf[2*jp+1][3], kb[2], kb[3]);
            }
        }

        // scale + mask + online softmax (rows g, g+8; 4 lanes/row)
        float mx0 = -1e30f, mx1 = -1e30f;
        #pragma unroll
        for (int nt = 0; nt < 8; nt++) {
            int2 mi = *(const int2*)&mkp[nt*8 + 2*t];
            float mvx = (1.0f - (float)mi.x) * (-1000000.0f);
            float mvy = (1.0f - (float)mi.y) * (-1000000.0f);
            sc[nt][0] = sc[nt][0]*0.125f + mvx;
            sc[nt][1] = sc[nt][1]*0.125f + mvy;
            sc[nt][2] = sc[nt][2]*0.125f + mvx;
            sc[nt][3] = sc[nt][3]*0.125f + mvy;
            mx0 = fmaxf(mx0, fmaxf(sc[nt][0], sc[nt][1]));
            mx1 = fmaxf(mx1, fmaxf(sc[nt][2], sc[nt][3]));
        }
        mx0 = fmaxf(mx0, __shfl_xor_sync(0xffffffffu, mx0, 1));
        mx0 = fmaxf(mx0, __shfl_xor_sync(0xffffffffu, mx0, 2));
        mx1 = fmaxf(mx1, __shfl_xor_sync(0xffffffffu, mx1, 1));
        mx1 = fmaxf(mx1, __shfl_xor_sync(0xffffffffu, mx1, 2));

        float mn0 = fmaxf(mold0, mx0), mn1 = fmaxf(mold1, mx1);
        float corr0 = __expf(mold0 - mn0), corr1 = __expf(mold1 - mn1);
        mold0 = mn0; mold1 = mn1;

        float sum0 = 0.f, sum1 = 0.f;
        #pragma unroll
        for (int nt = 0; nt < 8; nt++) {
            sc[nt][0] = __expf(sc[nt][0] - mn0);
            sc[nt][1] = __expf(sc[nt][1] - mn0);
            sc[nt][2] = __expf(sc[nt][2] - mn1);
            sc[nt][3] = __expf(sc[nt][3] - mn1);
            sum0 += sc[nt][0] + sc[nt][1];
            sum1 += sc[nt][2] + sc[nt][3];
        }
        sum0 += __shfl_xor_sync(0xffffffffu, sum0, 1);
        sum0 += __shfl_xor_sync(0xffffffffu, sum0, 2);
        sum1 += __shfl_xor_sync(0xffffffffu, sum1, 1);
        sum1 += __shfl_xor_sync(0xffffffffu, sum1, 2);
        l0 = l0*corr0 + sum0;
        l1 = l1*corr1 + sum1;
        #pragma unroll
        for (int nt = 0; nt < 8; nt++) {
            o[nt][0] *= corr0; o[nt][1] *= corr0;
            o[nt][2] *= corr1; o[nt][3] *= corr1;
        }

        // O += P V ; P packed straight from sc registers
        #pragma unroll
        for (int j = 0; j < 4; j++) {
            unsigned a0 = bf2(sc[2*j][0],   sc[2*j][1]);
            unsigned a1 = bf2(sc[2*j][2],   sc[2*j][3]);
            unsigned a2 = bf2(sc[2*j+1][0], sc[2*j+1][1]);
            unsigned a3 = bf2(sc[2*j+1][2], sc[2*j+1][3]);
            #pragma unroll
            for (int np = 0; np < 4; np++) {
                unsigned vb[4];
                int r = 16*j + rV, ch = 2*np + cV;
                ldsm4t(vb, VsB + r*128 + ((ch ^ r7) << 4));
                mma16(o[2*np],   a0, a1, a2, a3, vb[0], vb[1]);
                mma16(o[2*np+1], a0, a1, a2, a3, vb[2], vb[3]);
            }
        }
        __syncthreads();   // all warps done with stage st before it is refilled
    }

    // epilogue: normalize, write bf16 merged-head (b,l,d/2)
    float inv0 = 1.0f / l0, inv1 = 1.0f / l1;
    int row0 = q0 + w*16 + g;
    unsigned* d0 = g_AOh + ((size_t)b*LL + row0)*384 + h*32;
    unsigned* d1 = d0 + (size_t)8*384;
    #pragma unroll
    for (int nt = 0; nt < 8; nt++) {
        d0[nt*4 + t] = bf2(o[nt][0]*inv0, o[nt][1]*inv0);
        d1[nt*4 + t] = bf2(o[nt][2]*inv1, o[nt][3]*inv1);
    }
}

// =================== output projection (bf16 A from scratch) + bias + residual ===================
__global__ __launch_bounds__(256) void outproj_mma_kernel(
    const float* __restrict__ qin, const float* __restrict__ W,
    const float* __restrict__ bias)
{
    __shared__ unsigned As[128*32];
    __shared__ unsigned Bs[64*32];

    int tid = threadIdx.x, w = tid >> 5, lane = tid & 31;
    int g = lane >> 2, t = lane & 3;
    int wm = w & 3, wn = w >> 2;
    int m0 = blockIdx.x * 128, n0 = blockIdx.y * 64;

    int lrA = tid >> 1, cbA = (tid & 1) * 4;
    int lrB = tid >> 2, cbB = (tid & 3) * 2;
    const unsigned* Ap = g_AOh + (size_t)(m0 + lrA) * 384;
    const float*    Bp = W     + (size_t)(n0 + lrB) * DD;

    int r7 = lane & 7;
    int rA = r7 + 8*((lane >> 3) & 1), cA = lane >> 4;
    int rB = r7,                       cB = lane >> 3;
    unsigned AsB = saddr(As), BsB = saddr(Bs);

    float acc[2][4][4] = {};

    for (int k0 = 0; k0 < DD; k0 += 64) {
        const uint4* a4 = (const uint4*)(Ap + k0/2);
        #pragma unroll
        for (int i = 0; i < 4; i++) {
            int c = cbA + i;
            *(uint4*)(As + lrA*32 + ((c ^ (lrA & 7)) << 2)) = a4[c];
        }
        const float4* b4 = (const float4*)(Bp + k0);
        #pragma unroll
        for (int i = 0; i < 2; i++) { int c = cbB + i; store8(Bs, lrB, c, b4[2*c], b4[2*c+1]); }
        __syncthreads();

        #pragma unroll
        for (int jp = 0; jp < 2; jp++) {
            unsigned af[2][2][4];
            #pragma unroll
            for (int mt = 0; mt < 2; mt++)
                #pragma unroll
                for (int kk = 0; kk < 2; kk++) {
                    int r = wm*32 + mt*16 + rA;
                    int ch = 2*(2*jp + kk) + cA;
                    ldsm4(af[mt][kk], AsB + r*128 + ((ch ^ r7) << 4));
                }
            unsigned bf[4][4];
            #pragma unroll
            for (int nt = 0; nt < 4; nt++) {
                int r = wn*32 + nt*8 + rB;
                int ch = 4*jp + cB;
                ldsm4(bf[nt], BsB + r*128 + ((ch ^ r7) << 4));
            }
            #pragma unroll
            for (int mt = 0; mt < 2; mt++)
                #pragma unroll
                for (int nt = 0; nt < 4; nt++) {
                    mma16(acc[mt][nt], af[mt][0][0], af[mt][0][1], af[mt][0][2], af[mt][0][3],
                          bf[nt][0], bf[nt][1]);
                    mma16(acc[mt][nt], af[mt][1][0], af[mt][1][1], af[mt][1][2], af[mt][1][3],
                          bf[nt][2], bf[nt][3]);
                }
        }
        __syncthreads();
    }

    #pragma unroll
    for (int mt = 0; mt < 2; mt++) {
        #pragma unroll
        for (int nt = 0; nt < 4; nt++) {
            int m = m0 + wm*32 + mt*16 + g;
            int n = n0 + wn*32 + nt*8 + 2*t;
            float2 bi = *(const float2*)&bias[n];
            {
                float2 rs = *(const float2*)&qin[(size_t)m*DD + n];
                *(float2*)&g_X[(size_t)m*DD + n] =
                    make_float2(acc[mt][nt][0] + bi.x + rs.x, acc[mt][nt][1] + bi.y + rs.y);
            }
            {
                int m2 = m + 8;
                float2 rs = *(const float2*)&qin[(size_t)m2*DD + n];
                *(float2*)&g_X[(size_t)m2*DD + n] =
                    make_float2(acc[mt][nt][2] + bi.x + rs.x, acc[mt][nt][3] + bi.y + rs.y);
            }
        }
    }
}

// =================== LayerNorm ===================
__global__ __launch_bounds__(256) void ln_kernel(
    const float* __restrict__ gamma, const float* __restrict__ beta,
    float* __restrict__ out)
{
    __shared__ float sh[18];
    int row = blockIdx.x, tid = threadIdx.x;
    const float* x = g_X + (size_t)row * DD;
    float v0 = x[tid], v1 = x[tid+256], v2 = x[tid+512];
    float s  = v0 + v1 + v2;
    float sq = v0*v0 + v1*v1 + v2*v2;
    #pragma unroll
    for (int off = 16; off > 0; off >>= 1) {
        s  += __shfl_xor_sync(0xffffffffu, s,  off);
        sq += __shfl_xor_sync(0xffffffffu, sq, off);
    }
    int wid = tid >> 5;
    if ((tid & 31) == 0) { sh[wid] = s; sh[wid + 8] = sq; }
    __syncthreads();
    if (tid == 0) {
        float S = 0.f, Q2 = 0.f;
        #pragma unroll
        for (int i = 0; i < 8; i++) { S += sh[i]; Q2 += sh[i+8]; }
        float mu  = S  * (1.0f / 768.0f);
        float var = Q2 * (1.0f / 768.0f) - mu * mu;
        sh[16] = mu;
        sh[17] = rsqrtf(var + 1e-5f);
    }
    __syncthreads();
    float mu = sh[16], rstd = sh[17];
    float* o = out + (size_t)row * DD;
    o[tid]     = (v0 - mu) * rstd * gamma[tid]     + beta[tid];
    o[tid+256] = (v1 - mu) * rstd * gamma[tid+256] + beta[tid+256];
    o[tid+512] = (v2 - mu) * rstd * gamma[tid+512] + beta[tid+512];
}

// =================== launch ===================
extern "C" void kernel_launch(void* const* d_in, const int* in_sizes, int n_in,
                              void* d_out, int out_size)
{
    const float* q     = (const float*)d_in[0];
    const float* k     = (const float*)d_in[1];
    const float* v     = (const float*)d_in[2];
    const int*   mask  = (const int*)  d_in[3];
    const float* Wq    = (const float*)d_in[4];
    const float* Wk    = (const float*)d_in[5];
    const float* Wv    = (const float*)d_in[6];
    const float* W     = (const float*)d_in[7];
    const float* bias  = (const float*)d_in[8];
    const float* gamma = (const float*)d_in[9];
    const float* beta  = (const float*)d_in[10];
    float* out = (float*)d_out;

    cudaFuncSetAttribute(attn_mma_kernel, cudaFuncAttributeMaxDynamicSharedMemorySize, ATTN_SMEM);

    qkv_mma_kernel    <<<dim3(MTOT/128, DD/64, 3), 256>>>(q, k, v, Wq, Wk, Wv);
    attn_mma_kernel   <<<dim3(LL/128, BB*HH), 256, ATTN_SMEM>>>(mask);
    outproj_mma_kernel<<<dim3(MTOT/128, DD/64), 256>>>(q, W, bias);
    ln_kernel         <<<MTOT, 256>>>(gamma, beta, out);
}

// round 11
// speedup vs baseline: 2.8838x; 1.0270x over previous
#include <cuda_runtime.h>
#include <math.h>

#define BB   2
#define LL   2048
#define SS   2048
#define DD   768
#define HH   12
#define HDIM 64
#define MTOT (BB*LL)   // 4096
#define LOG2E 1.4426950408889634f
#define SCALE2 (0.125f * LOG2E)

// ---------------- scratch (no allocations allowed) ----------------
__device__ unsigned g_Qh [(size_t)BB*HH*LL*HDIM/2];   // bf16x2 (b,h,l,hd/2)
__device__ unsigned g_Kh [(size_t)BB*HH*SS*HDIM/2];
__device__ unsigned g_Vh [(size_t)BB*HH*SS*HDIM/2];
__device__ unsigned g_AOh[(size_t)MTOT*DD/2];         // attention out bf16, (b,l,d/2)
__device__ float    g_X  [(size_t)MTOT*DD];           // pre-LN residual fp32
__device__ float    g_mkf[(size_t)BB*SS];             // additive mask * log2e

// ---------------- helpers ----------------
__device__ __forceinline__ unsigned bf2(float lo, float hi) {
    unsigned r; asm("cvt.rn.bf16x2.f32 %0, %1, %2;" : "=r"(r) : "f"(hi), "f"(lo));
    return r;
}
__device__ __forceinline__ void mma16(float* c, unsigned a0, unsigned a1, unsigned a2, unsigned a3,
                                      unsigned b0, unsigned b1) {
    asm volatile(
        "mma.sync.aligned.m16n8k16.row.col.f32.bf16.bf16.f32 "
        "{%0,%1,%2,%3},{%4,%5,%6,%7},{%8,%9},{%0,%1,%2,%3};"
        : "+f"(c[0]), "+f"(c[1]), "+f"(c[2]), "+f"(c[3])
        : "r"(a0), "r"(a1), "r"(a2), "r"(a3), "r"(b0), "r"(b1));
}
__device__ __forceinline__ void ldsm4(unsigned* r, unsigned a) {
    asm volatile("ldmatrix.sync.aligned.m8n8.x4.shared.b16 {%0,%1,%2,%3}, [%4];"
        : "=r"(r[0]), "=r"(r[1]), "=r"(r[2]), "=r"(r[3]) : "r"(a));
}
__device__ __forceinline__ void ldsm4t(unsigned* r, unsigned a) {
    asm volatile("ldmatrix.sync.aligned.m8n8.x4.trans.shared.b16 {%0,%1,%2,%3}, [%4];"
        : "=r"(r[0]), "=r"(r[1]), "=r"(r[2]), "=r"(r[3]) : "r"(a));
}
__device__ __forceinline__ unsigned saddr(const void* p) {
    return (unsigned)__cvta_generic_to_shared(p);
}
__device__ __forceinline__ void cpa16(unsigned sdst, const void* gsrc) {
    asm volatile("cp.async.cg.shared.global [%0], [%1], 16;" :: "r"(sdst), "l"(gsrc));
}
// tile: 128B rows (32 uints = 8 chunks of 16B), swizzle chunk ^= row&7
__device__ __forceinline__ void store8(unsigned* tile, int row, int chunk,
                                       float4 v0, float4 v1) {
    *(uint4*)(tile + row*32 + ((chunk ^ (row & 7)) << 2)) =
        make_uint4(bf2(v0.x, v0.y), bf2(v0.z, v0.w), bf2(v1.x, v1.y), bf2(v1.z, v1.w));
}

// =================== mask precompute ===================
__global__ __launch_bounds__(256) void maskf_kernel(const int* __restrict__ maskp) {
    int i = blockIdx.x * 256 + threadIdx.x;
    g_mkf[i] = (1.0f - (float)maskp[i]) * (-1000000.0f * LOG2E);
}

// =================== QKV projection GEMM (bf16 mma + ldmatrix, reg-pipelined) ===================
__global__ __launch_bounds__(256) void qkv_mma_kernel(
    const float* __restrict__ qin, const float* __restrict__ kin, const float* __restrict__ vin,
    const float* __restrict__ Wq,  const float* __restrict__ Wk,  const float* __restrict__ Wv)
{
    __shared__ unsigned As[128*32];
    __shared__ unsigned Bs[64*32];

    int which = blockIdx.z;
    const float* A  = (which == 0) ? qin : (which == 1) ? kin : vin;
    const float* Wt = (which == 0) ? Wq  : (which == 1) ? Wk  : Wv;
    unsigned* Out   = (which == 0) ? g_Qh : (which == 1) ? g_Kh : g_Vh;

    int tid = threadIdx.x, w = tid >> 5, lane = tid & 31;
    int g = lane >> 2, t = lane & 3;
    int wm = w & 3, wn = w >> 2;
    int m0 = blockIdx.x * 128, n0 = blockIdx.y * 64;

    int lrA = tid >> 1, cbA = (tid & 1) * 4;
    int lrB = tid >> 2, cbB = (tid & 3) * 2;
    const float* Ap = A  + (size_t)(m0 + lrA) * DD;
    const float* Bp = Wt + (size_t)(n0 + lrB) * DD;

    int r7 = lane & 7;
    int rA = r7 + 8*((lane >> 3) & 1), cA = lane >> 4;
    int rB = r7,                       cB = lane >> 3;
    unsigned AsB = saddr(As), BsB = saddr(Bs);

    float acc[2][4][4] = {};
    float4 ra[4][2], rb[2][2];

    // prologue load
    {
        const float4* a4 = (const float4*)Ap;
        #pragma unroll
        for (int i = 0; i < 4; i++) { int c = cbA+i; ra[i][0] = a4[2*c]; ra[i][1] = a4[2*c+1]; }
        const float4* b4 = (const float4*)Bp;
        #pragma unroll
        for (int i = 0; i < 2; i++) { int c = cbB+i; rb[i][0] = b4[2*c]; rb[i][1] = b4[2*c+1]; }
    }

    for (int k0 = 0; k0 < DD; k0 += 64) {
        #pragma unroll
        for (int i = 0; i < 4; i++) store8(As, lrA, cbA+i, ra[i][0], ra[i][1]);
        #pragma unroll
        for (int i = 0; i < 2; i++) store8(Bs, lrB, cbB+i, rb[i][0], rb[i][1]);
        __syncthreads();

        if (k0 + 64 < DD) {   // prefetch next slab into regs (overlaps mma)
            const float4* a4 = (const float4*)(Ap + k0 + 64);
            #pragma unroll
            for (int i = 0; i < 4; i++) { int c = cbA+i; ra[i][0] = a4[2*c]; ra[i][1] = a4[2*c+1]; }
            const float4* b4 = (const float4*)(Bp + k0 + 64);
            #pragma unroll
            for (int i = 0; i < 2; i++) { int c = cbB+i; rb[i][0] = b4[2*c]; rb[i][1] = b4[2*c+1]; }
        }

        #pragma unroll
        for (int jp = 0; jp < 2; jp++) {
            unsigned af[2][2][4];
            #pragma unroll
            for (int mt = 0; mt < 2; mt++)
                #pragma unroll
                for (int kk = 0; kk < 2; kk++) {
                    int r = wm*32 + mt*16 + rA;
                    int ch = 2*(2*jp + kk) + cA;
                    ldsm4(af[mt][kk], AsB + r*128 + ((ch ^ r7) << 4));
                }
            unsigned bf[4][4];
            #pragma unroll
            for (int nt = 0; nt < 4; nt++) {
                int r = wn*32 + nt*8 + rB;
                int ch = 4*jp + cB;
                ldsm4(bf[nt], BsB + r*128 + ((ch ^ r7) << 4));
            }
            #pragma unroll
            for (int mt = 0; mt < 2; mt++)
                #pragma unroll
                for (int nt = 0; nt < 4; nt++) {
                    mma16(acc[mt][nt], af[mt][0][0], af[mt][0][1], af[mt][0][2], af[mt][0][3],
                          bf[nt][0], bf[nt][1]);
                    mma16(acc[mt][nt], af[mt][1][0], af[mt][1][1], af[mt][1][2], af[mt][1][3],
                          bf[nt][2], bf[nt][3]);
                }
        }
        __syncthreads();
    }

    // epilogue: bf16 pairs, (b,h,l,hd/2)
    #pragma unroll
    for (int mt = 0; mt < 2; mt++) {
        #pragma unroll
        for (int nt = 0; nt < 4; nt++) {
            int m = m0 + wm*32 + mt*16 + g;
            int n = n0 + wn*32 + nt*8 + 2*t;
            int h = n >> 6, hp = (n & 63) >> 1;
            int bb = m >> 11, l = m & (LL-1);
            Out[(((size_t)bb*HH + h)*LL + l)*32 + hp] = bf2(acc[mt][nt][0], acc[mt][nt][1]);
            int m2 = m + 8; bb = m2 >> 11; l = m2 & (LL-1);
            Out[(((size_t)bb*HH + h)*LL + l)*32 + hp] = bf2(acc[mt][nt][2], acc[mt][nt][3]);
        }
    }
}

// =================== flash attention: bf16, 3-stage cp.async ring, occ 2 ===================
// grid: (L/128, B*H), 256 threads (8 warps; warp w owns q-rows w*16..w*16+15)
// dyn smem: Qs[128*32] | KV[3][K|V][64*32] | mkf[3][64]
#define ATTN_SMEM ((128*32 + 3*2*64*32) * 4 + 3*64*4)

__global__ __launch_bounds__(256, 2) void attn_mma_kernel()
{
    extern __shared__ unsigned dyn[];
    unsigned* Qs = dyn;                   // 128*32
    unsigned* KV = Qs + 128*32;           // [stage][K|V][64*32]
    float* mks   = (float*)(KV + 3*2*64*32);  // [stage][64]

    int tid = threadIdx.x, w = tid >> 5, lane = tid & 31;
    int g = lane >> 2, t = lane & 3;
    int bh = blockIdx.y;
    int b  = bh / HH, h = bh % HH;
    int q0 = blockIdx.x * 128;

    const unsigned* Qg = g_Qh + (size_t)bh * LL * 32;
    const unsigned* Kg = g_Kh + (size_t)bh * SS * 32;
    const unsigned* Vg = g_Vh + (size_t)bh * SS * 32;
    const float*    Mg = g_mkf + (size_t)b * SS;

    int r7 = lane & 7;
    unsigned QsB = saddr(Qs), KVB = saddr(KV), mkB = saddr(mks);

    int prow = tid >> 2;            // 0..63
    int pcb  = (tid & 3) * 2;       // chunk base {0,2,4,6}
    unsigned kdstB = KVB + prow*128 + (((pcb    ) ^ (prow & 7)) << 4);
    unsigned kdstB2= KVB + prow*128 + (((pcb + 1) ^ (prow & 7)) << 4);

    // prefetch KV tile 'ti' into stage 'st'
    auto prefetch = [&](int ti, int st) {
        int s0 = ti * 64;
        const uint4* kg = (const uint4*)(Kg + (size_t)(s0 + prow) * 32);
        const uint4* vg = (const uint4*)(Vg + (size_t)(s0 + prow) * 32);
        unsigned off = st * 16384;
        cpa16(kdstB  + off,        kg + pcb);
        cpa16(kdstB2 + off,        kg + pcb + 1);
        cpa16(kdstB  + off + 8192, vg + pcb);
        cpa16(kdstB2 + off + 8192, vg + pcb + 1);
        if (tid < 16) cpa16(mkB + st*256 + tid*16, Mg + s0 + tid*4);
        asm volatile("cp.async.commit_group;");
    };

    // load Q tile (plain copy, once)
    {
        int qrow = tid >> 1, qcb = (tid & 1) * 4;
        const uint4* src = (const uint4*)(Qg + (size_t)(q0 + qrow) * 32);
        #pragma unroll
        for (int i = 0; i < 4; i++) {
            int c = qcb + i;
            *(uint4*)(Qs + qrow*32 + ((c ^ (qrow & 7)) << 2)) = src[c];
        }
    }

    prefetch(0, 0);
    prefetch(1, 1);
    __syncthreads();

    // Q fragments (resident)
    unsigned qf[4][4];
    {
        int r = 16*w + r7 + 8*((lane >> 3) & 1);
        int cq = lane >> 4;
        #pragma unroll
        for (int kc = 0; kc < 4; kc++) {
            int ch = 2*kc + cq;
            ldsm4(qf[kc], QsB + r*128 + ((ch ^ r7) << 4));
        }
    }

    float o[8][4] = {};
    float mold0 = -1e30f, mold1 = -1e30f, l0 = 0.f, l1 = 0.f;

    int rK = r7,                       cK = lane >> 3;   // K b-frag
    int rV = r7 + 8*((lane >> 3) & 1), cV = lane >> 4;   // V trans b-frag

    const int NT = SS / 64;
    for (int it = 0; it < NT; it++) {
        int st = it % 3;
        if (it + 1 < NT) asm volatile("cp.async.wait_group 1;");
        else             asm volatile("cp.async.wait_group 0;");
        __syncthreads();
        // safe: sync proves all warps finished tile it-1 (stage (it+2)%3 == (it-1)%3)
        if (it + 2 < NT) prefetch(it + 2, (it + 2) % 3);

        unsigned KsB = KVB + st*16384;
        unsigned VsB = KsB + 8192;
        const float* mkp = mks + st*64;

        // scores S(16x64) = Q K^T
        float sc[8][4] = {};
        #pragma unroll
        for (int jp = 0; jp < 2; jp++) {
            #pragma unroll
            for (int nt = 0; nt < 8; nt++) {
                unsigned kb[4];
                int r = nt*8 + rK, ch = 4*jp + cK;
                ldsm4(kb, KsB + r*128 + ((ch ^ rK) << 4));
                mma16(sc[nt], qf[2*jp][0], qf[2*jp][1], qf[2*jp][2], qf[2*jp][3], kb[0], kb[1]);
                mma16(sc[nt], qf[2*jp+1][0], qf[2*jp+1][1], qf[2*jp+1][2], qf[2*jp+1][3], kb[2], kb[3]);
            }
        }

        // scale + mask + online softmax in log2 domain (rows g, g+8; 4 lanes/row)
        float mx0 = -1e30f, mx1 = -1e30f;
        #pragma unroll
        for (int nt = 0; nt < 8; nt++) {
            float2 mv = *(const float2*)&mkp[nt*8 + 2*t];
            sc[nt][0] = sc[nt][0]*SCALE2 + mv.x;
            sc[nt][1] = sc[nt][1]*SCALE2 + mv.y;
            sc[nt][2] = sc[nt][2]*SCALE2 + mv.x;
            sc[nt][3] = sc[nt][3]*SCALE2 + mv.y;
            mx0 = fmaxf(mx0, fmaxf(sc[nt][0], sc[nt][1]));
            mx1 = fmaxf(mx1, fmaxf(sc[nt][2], sc[nt][3]));
        }
        mx0 = fmaxf(mx0, __shfl_xor_sync(0xffffffffu, mx0, 1));
        mx0 = fmaxf(mx0, __shfl_xor_sync(0xffffffffu, mx0, 2));
        mx1 = fmaxf(mx1, __shfl_xor_sync(0xffffffffu, mx1, 1));
        mx1 = fmaxf(mx1, __shfl_xor_sync(0xffffffffu, mx1, 2));

        float mn0 = fmaxf(mold0, mx0), mn1 = fmaxf(mold1, mx1);
        float corr0 = exp2f(mold0 - mn0), corr1 = exp2f(mold1 - mn1);
        mold0 = mn0; mold1 = mn1;

        float sum0 = 0.f, sum1 = 0.f;
        #pragma unroll
        for (int nt = 0; nt < 8; nt++) {
            sc[nt][0] = exp2f(sc[nt][0] - mn0);
            sc[nt][1] = exp2f(sc[nt][1] - mn0);
            sc[nt][2] = exp2f(sc[nt][2] - mn1);
            sc[nt][3] = exp2f(sc[nt][3] - mn1);
            sum0 += sc[nt][0] + sc[nt][1];
            sum1 += sc[nt][2] + sc[nt][3];
        }
        sum0 += __shfl_xor_sync(0xffffffffu, sum0, 1);
        sum0 += __shfl_xor_sync(0xffffffffu, sum0, 2);
        sum1 += __shfl_xor_sync(0xffffffffu, sum1, 1);
        sum1 += __shfl_xor_sync(0xffffffffu, sum1, 2);
        l0 = l0*corr0 + sum0;
        l1 = l1*corr1 + sum1;
        #pragma unroll
        for (int nt = 0; nt < 8; nt++) {
            o[nt][0] *= corr0; o[nt][1] *= corr0;
            o[nt][2] *= corr1; o[nt][3] *= corr1;
        }

        // O += P V ; P packed straight from sc registers
        #pragma unroll
        for (int j = 0; j < 4; j++) {
            unsigned a0 = bf2(sc[2*j][0],   sc[2*j][1]);
            unsigned a1 = bf2(sc[2*j][2],   sc[2*j][3]);
            unsigned a2 = bf2(sc[2*j+1][0], sc[2*j+1][1]);
            unsigned a3 = bf2(sc[2*j+1][2], sc[2*j+1][3]);
            #pragma unroll
            for (int np = 0; np < 4; np++) {
                unsigned vb[4];
                int r = 16*j + rV, ch = 2*np + cV;
                ldsm4t(vb, VsB + r*128 + ((ch ^ r7) << 4));
                mma16(o[2*np],   a0, a1, a2, a3, vb[0], vb[1]);
                mma16(o[2*np+1], a0, a1, a2, a3, vb[2], vb[3]);
            }
        }
    }

    // epilogue: normalize, write bf16 merged-head (b,l,d/2)
    float inv0 = 1.0f / l0, inv1 = 1.0f / l1;
    int row0 = q0 + w*16 + g;
    unsigned* d0 = g_AOh + ((size_t)b*LL + row0)*384 + h*32;
    unsigned* d1 = d0 + (size_t)8*384;
    #pragma unroll
    for (int nt = 0; nt < 8; nt++) {
        d0[nt*4 + t] = bf2(o[nt][0]*inv0, o[nt][1]*inv0);
        d1[nt*4 + t] = bf2(o[nt][2]*inv1, o[nt][3]*inv1);
    }
}

// =================== output projection (bf16 A, reg-pipelined) + bias + residual ===================
__global__ __launch_bounds__(256) void outproj_mma_kernel(
    const float* __restrict__ qin, const float* __restrict__ W,
    const float* __restrict__ bias)
{
    __shared__ unsigned As[128*32];
    __shared__ unsigned Bs[64*32];

    int tid = threadIdx.x, w = tid >> 5, lane = tid & 31;
    int g = lane >> 2, t = lane & 3;
    int wm = w & 3, wn = w >> 2;
    int m0 = blockIdx.x * 128, n0 = blockIdx.y * 64;

    int lrA = tid >> 1, cbA = (tid & 1) * 4;
    int lrB = tid >> 2, cbB = (tid & 3) * 2;
    const unsigned* Ap = g_AOh + (size_t)(m0 + lrA) * 384;
    const float*    Bp = W     + (size_t)(n0 + lrB) * DD;

    int r7 = lane & 7;
    int rA = r7 + 8*((lane >> 3) & 1), cA = lane >> 4;
    int rB = r7,                       cB = lane >> 3;
    unsigned AsB = saddr(As), BsB = saddr(Bs);

    float acc[2][4][4] = {};
    uint4  raU[4];
    float4 rb[2][2];

    {
        const uint4* a4 = (const uint4*)Ap;
        #pragma unroll
        for (int i = 0; i < 4; i++) raU[i] = a4[cbA+i];
        const float4* b4 = (const float4*)Bp;
        #pragma unroll
        for (int i = 0; i < 2; i++) { int c = cbB+i; rb[i][0] = b4[2*c]; rb[i][1] = b4[2*c+1]; }
    }

    for (int k0 = 0; k0 < DD; k0 += 64) {
        #pragma unroll
        for (int i = 0; i < 4; i++) {
            int c = cbA + i;
            *(uint4*)(As + lrA*32 + ((c ^ (lrA & 7)) << 2)) = raU[i];
        }
        #pragma unroll
        for (int i = 0; i < 2; i++) store8(Bs, lrB, cbB+i, rb[i][0], rb[i][1]);
        __syncthreads();

        if (k0 + 64 < DD) {
            const uint4* a4 = (const uint4*)(Ap + (k0+64)/2);
            #pragma unroll
            for (int i = 0; i < 4; i++) raU[i] = a4[cbA+i];
            const float4* b4 = (const float4*)(Bp + k0 + 64);
            #pragma unroll
            for (int i = 0; i < 2; i++) { int c = cbB+i; rb[i][0] = b4[2*c]; rb[i][1] = b4[2*c+1]; }
        }

        #pragma unroll
        for (int jp = 0; jp < 2; jp++) {
            unsigned af[2][2][4];
            #pragma unroll
            for (int mt = 0; mt < 2; mt++)
                #pragma unroll
                for (int kk = 0; kk < 2; kk++) {
                    int r = wm*32 + mt*16 + rA;
                    int ch = 2*(2*jp + kk) + cA;
                    ldsm4(af[mt][kk], AsB + r*128 + ((ch ^ r7) << 4));
                }
            unsigned bf[4][4];
            #pragma unroll
            for (int nt = 0; nt < 4; nt++) {
                int r = wn*32 + nt*8 + rB;
                int ch = 4*jp + cB;
                ldsm4(bf[nt], BsB + r*128 + ((ch ^ r7) << 4));
            }
            #pragma unroll
            for (int mt = 0; mt < 2; mt++)
                #pragma unroll
                for (int nt = 0; nt < 4; nt++) {
                    mma16(acc[mt][nt], af[mt][0][0], af[mt][0][1], af[mt][0][2], af[mt][0][3],
                          bf[nt][0], bf[nt][1]);
                    mma16(acc[mt][nt], af[mt][1][0], af[mt][1][1], af[mt][1][2], af[mt][1][3],
                          bf[nt][2], bf[nt][3]);
                }
        }
        __syncthreads();
    }

    #pragma unroll
    for (int mt = 0; mt < 2; mt++) {
        #pragma unroll
        for (int nt = 0; nt < 4; nt++) {
            int m = m0 + wm*32 + mt*16 + g;
            int n = n0 + wn*32 + nt*8 + 2*t;
            float2 bi = *(const float2*)&bias[n];
            {
                float2 rs = *(const float2*)&qin[(size_t)m*DD + n];
                *(float2*)&g_X[(size_t)m*DD + n] =
                    make_float2(acc[mt][nt][0] + bi.x + rs.x, acc[mt][nt][1] + bi.y + rs.y);
            }
            {
                int m2 = m + 8;
                float2 rs = *(const float2*)&qin[(size_t)m2*DD + n];
                *(float2*)&g_X[(size_t)m2*DD + n] =
                    make_float2(acc[mt][nt][2] + bi.x + rs.x, acc[mt][nt][3] + bi.y + rs.y);
            }
        }
    }
}

// =================== LayerNorm ===================
__global__ __launch_bounds__(256) void ln_kernel(
    const float* __restrict__ gamma, const float* __restrict__ beta,
    float* __restrict__ out)
{
    __shared__ float sh[18];
    int row = blockIdx.x, tid = threadIdx.x;
    const float* x = g_X + (size_t)row * DD;
    float v0 = x[tid], v1 = x[tid+256], v2 = x[tid+512];
    float s  = v0 + v1 + v2;
    float sq = v0*v0 + v1*v1 + v2*v2;
    #pragma unroll
    for (int off = 16; off > 0; off >>= 1) {
        s  += __shfl_xor_sync(0xffffffffu, s,  off);
        sq += __shfl_xor_sync(0xffffffffu, sq, off);
    }
    int wid = tid >> 5;
    if ((tid & 31) == 0) { sh[wid] = s; sh[wid + 8] = sq; }
    __syncthreads();
    if (tid == 0) {
        float S = 0.f, Q2 = 0.f;
        #pragma unroll
        for (int i = 0; i < 8; i++) { S += sh[i]; Q2 += sh[i+8]; }
        float mu  = S  * (1.0f / 768.0f);
        float var = Q2 * (1.0f / 768.0f) - mu * mu;
        sh[16] = mu;
        sh[17] = rsqrtf(var + 1e-5f);
    }
    __syncthreads();
    float mu = sh[16], rstd = sh[17];
    float* o = out + (size_t)row * DD;
    o[tid]     = (v0 - mu) * rstd * gamma[tid]     + beta[tid];
    o[tid+256] = (v1 - mu) * rstd * gamma[tid+256] + beta[tid+256];
    o[tid+512] = (v2 - mu) * rstd * gamma[tid+512] + beta[tid+512];
}

// =================== launch ===================
extern "C" void kernel_launch(void* const* d_in, const int* in_sizes, int n_in,
                              void* d_out, int out_size)
{
    const float* q     = (const float*)d_in[0];
    const float* k     = (const float*)d_in[1];
    const float* v     = (const float*)d_in[2];
    const int*   mask  = (const int*)  d_in[3];
    const float* Wq    = (const float*)d_in[4];
    const float* Wk    = (const float*)d_in[5];
    const float* Wv    = (const float*)d_in[6];
    const float* W     = (const float*)d_in[7];
    const float* bias  = (const float*)d_in[8];
    const float* gamma = (const float*)d_in[9];
    const float* beta  = (const float*)d_in[10];
    float* out = (float*)d_out;

    cudaFuncSetAttribute(attn_mma_kernel, cudaFuncAttributeMaxDynamicSharedMemorySize, ATTN_SMEM);

    maskf_kernel      <<<BB*SS/256, 256>>>(mask);
    qkv_mma_kernel    <<<dim3(MTOT/128, DD/64, 3), 256>>>(q, k, v, Wq, Wk, Wv);
    attn_mma_kernel   <<<dim3(LL/128, BB*HH), 256, ATTN_SMEM>>>();
    outproj_mma_kernel<<<dim3(MTOT/128, DD/64), 256>>>(q, W, bias);
    ln_kernel         <<<MTOT, 256>>>(gamma, beta, out);
}

// round 14
// speedup vs baseline: 4.1990x; 1.4561x over previous
#include <cuda_runtime.h>
#include <math.h>

#define BB   2
#define LL   2048
#define SS   2048
#define DD   768
#define HH   12
#define HDIM 64
#define MTOT (BB*LL)   // 4096
#define LOG2E 1.4426950408889634f
#define SCALE2 (0.125f * LOG2E)

// ---------------- scratch (no allocations allowed) ----------------
__device__ unsigned g_Qh [(size_t)BB*HH*LL*HDIM/2];   // bf16x2 (b,h,l,hd/2)
__device__ unsigned g_Kh [(size_t)BB*HH*SS*HDIM/2];
__device__ unsigned g_Vh [(size_t)BB*HH*SS*HDIM/2];
__device__ unsigned g_AOh[(size_t)MTOT*DD/2];         // attention out bf16, (b,l,d/2)
__device__ float    g_X  [(size_t)MTOT*DD];           // pre-LN residual fp32
__device__ float    g_mkf[(size_t)BB*SS];             // additive mask * log2e
// bf16 copies of inputs/weights
__device__ unsigned g_qb [(size_t)MTOT*DD/2];
__device__ unsigned g_kb [(size_t)MTOT*DD/2];
__device__ unsigned g_vb [(size_t)MTOT*DD/2];
__device__ unsigned g_Wqb[(size_t)DD*DD/2];
__device__ unsigned g_Wkb[(size_t)DD*DD/2];
__device__ unsigned g_Wvb[(size_t)DD*DD/2];
__device__ unsigned g_Wob[(size_t)DD*DD/2];

// ---------------- helpers ----------------
__device__ __forceinline__ unsigned bf2(float lo, float hi) {
    unsigned r; asm("cvt.rn.bf16x2.f32 %0, %1, %2;" : "=r"(r) : "f"(hi), "f"(lo));
    return r;
}
__device__ __forceinline__ void mma16(float* c, unsigned a0, unsigned a1, unsigned a2, unsigned a3,
                                      unsigned b0, unsigned b1) {
    asm volatile(
        "mma.sync.aligned.m16n8k16.row.col.f32.bf16.bf16.f32 "
        "{%0,%1,%2,%3},{%4,%5,%6,%7},{%8,%9},{%0,%1,%2,%3};"
        : "+f"(c[0]), "+f"(c[1]), "+f"(c[2]), "+f"(c[3])
        : "r"(a0), "r"(a1), "r"(a2), "r"(a3), "r"(b0), "r"(b1));
}
__device__ __forceinline__ void ldsm4(unsigned* r, unsigned a) {
    asm volatile("ldmatrix.sync.aligned.m8n8.x4.shared.b16 {%0,%1,%2,%3}, [%4];"
        : "=r"(r[0]), "=r"(r[1]), "=r"(r[2]), "=r"(r[3]) : "r"(a));
}
__device__ __forceinline__ void ldsm4t(unsigned* r, unsigned a) {
    asm volatile("ldmatrix.sync.aligned.m8n8.x4.trans.shared.b16 {%0,%1,%2,%3}, [%4];"
        : "=r"(r[0]), "=r"(r[1]), "=r"(r[2]), "=r"(r[3]) : "r"(a));
}
__device__ __forceinline__ unsigned saddr(const void* p) {
    return (unsigned)__cvta_generic_to_shared(p);
}
__device__ __forceinline__ void cpa16(unsigned sdst, const void* gsrc) {
    asm volatile("cp.async.cg.shared.global [%0], [%1], 16;" :: "r"(sdst), "l"(gsrc));
}

// =================== tiny preprocess kernels ===================
__global__ __launch_bounds__(256) void maskf_kernel(const int* __restrict__ maskp) {
    int i = blockIdx.x * 256 + threadIdx.x;
    g_mkf[i] = (1.0f - (float)maskp[i]) * (-1000000.0f * LOG2E);
}
// convert fp32 -> bf16x2 (2 pairs / thread); which selects destination
__global__ __launch_bounds__(256) void cvt_kernel(const float* __restrict__ src, int which) {
    unsigned* dst = (which == 0) ? g_qb  : (which == 1) ? g_kb  : (which == 2) ? g_vb :
                    (which == 3) ? g_Wqb : (which == 4) ? g_Wkb : (which == 5) ? g_Wvb : g_Wob;
    size_t i = (size_t)blockIdx.x * 256 + threadIdx.x;
    float4 v = ((const float4*)src)[i];
    ((uint2*)dst)[i] = make_uint2(bf2(v.x, v.y), bf2(v.z, v.w));
}

// =================== shared GEMM core: 3-stage cp.async, BM=128 BN=64 BK=64 ===================
#define GEMM_SMEM (3*(128*32 + 64*32)*4)

struct GemmCore {
    unsigned AsB0, BsB0;
    int lrA, cbA, lrB, cbB;
    const uint4 *agbase, *bgbase;
    int r7, rA, cA, rB, cB;
    int wm, wn;
};

__device__ __forceinline__ GemmCore gemm_init(const unsigned* Ab, const unsigned* Bb,
                                              int m0, int n0, unsigned* dyn) {
    GemmCore gc;
    int tid = threadIdx.x, lane = tid & 31;
    gc.lrA = tid >> 1; gc.cbA = (tid & 1) * 4;
    gc.lrB = tid >> 2; gc.cbB = (tid & 3) * 2;
    gc.agbase = (const uint4*)(Ab + (size_t)(m0 + gc.lrA) * (DD/2));
    gc.bgbase = (const uint4*)(Bb + (size_t)(n0 + gc.lrB) * (DD/2));
    gc.r7 = lane & 7;
    gc.rA = gc.r7 + 8*((lane >> 3) & 1); gc.cA = lane >> 4;
    gc.rB = gc.r7;                       gc.cB = lane >> 3;
    int w = tid >> 5;
    gc.wm = w & 3; gc.wn = w >> 2;
    gc.AsB0 = saddr(dyn);
    gc.BsB0 = saddr(dyn + 3*128*32);
    return gc;
}

__device__ __forceinline__ void gemm_prefetch(const GemmCore& gc, int ti, int st) {
    unsigned offA = gc.AsB0 + st*16384 + gc.lrA*128;
    const uint4* ag = gc.agbase + ti*8;
    #pragma unroll
    for (int i = 0; i < 4; i++) {
        int c = gc.cbA + i;
        cpa16(offA + ((c ^ (gc.lrA & 7)) << 4), ag + c);
    }
    unsigned offB = gc.BsB0 + st*8192 + gc.lrB*128;
    const uint4* bg = gc.bgbase + ti*8;
    #pragma unroll
    for (int i = 0; i < 2; i++) {
        int c = gc.cbB + i;
        cpa16(offB + ((c ^ (gc.lrB & 7)) << 4), bg + c);
    }
    asm volatile("cp.async.commit_group;");
}

__device__ __forceinline__ void gemm_mainloop(const GemmCore& gc, float acc[2][4][4]) {
    const int NT = DD / 64;   // 12
    gemm_prefetch(gc, 0, 0);
    gemm_prefetch(gc, 1, 1);
    for (int it = 0; it < NT; it++) {
        int st = it % 3;
        if (it + 1 < NT) asm volatile("cp.async.wait_group 1;");
        else             asm volatile("cp.async.wait_group 0;");
        __syncthreads();
        if (it + 2 < NT) gemm_prefetch(gc, it + 2, (it + 2) % 3);

        unsigned AsB = gc.AsB0 + st*16384;
        unsigned BsB = gc.BsB0 + st*8192;
        #pragma unroll
        for (int jp = 0; jp < 2; jp++) {
            unsigned af[2][2][4];
            #pragma unroll
            for (int mt = 0; mt < 2; mt++)
                #pragma unroll
                for (int kk = 0; kk < 2; kk++) {
                    int r = gc.wm*32 + mt*16 + gc.rA;
                    int ch = 2*(2*jp + kk) + gc.cA;
                    ldsm4(af[mt][kk], AsB + r*128 + ((ch ^ gc.r7) << 4));
                }
            unsigned bf[4][4];
            #pragma unroll
            for (int nt = 0; nt < 4; nt++) {
                int r = gc.wn*32 + nt*8 + gc.rB;
                int ch = 4*jp + gc.cB;
                ldsm4(bf[nt], BsB + r*128 + ((ch ^ gc.r7) << 4));
            }
            #pragma unroll
            for (int mt = 0; mt < 2; mt++)
                #pragma unroll
                for (int nt = 0; nt < 4; nt++) {
                    mma16(acc[mt][nt], af[mt][0][0], af[mt][0][1], af[mt][0][2], af[mt][0][3],
                          bf[nt][0], bf[nt][1]);
                    mma16(acc[mt][nt], af[mt][1][0], af[mt][1][1], af[mt][1][2], af[mt][1][3],
                          bf[nt][2], bf[nt][3]);
                }
        }
        __syncthreads();
    }
}

// =================== QKV projection ===================
__global__ __launch_bounds__(256, 2) void qkv_mma_kernel()
{
    extern __shared__ unsigned dyn[];
    int which = blockIdx.z;
    const unsigned* Ab = (which == 0) ? g_qb  : (which == 1) ? g_kb  : g_vb;
    const unsigned* Bb = (which == 0) ? g_Wqb : (which == 1) ? g_Wkb : g_Wvb;
    unsigned* Out      = (which == 0) ? g_Qh  : (which == 1) ? g_Kh  : g_Vh;

    int m0 = blockIdx.x * 128, n0 = blockIdx.y * 64;
    GemmCore gc = gemm_init(Ab, Bb, m0, n0, dyn);

    float acc[2][4][4] = {};
    gemm_mainloop(gc, acc);

    int lane = threadIdx.x & 31, g = lane >> 2, t = lane & 3;
    #pragma unroll
    for (int mt = 0; mt < 2; mt++) {
        #pragma unroll
        for (int nt = 0; nt < 4; nt++) {
            int m = m0 + gc.wm*32 + mt*16 + g;
            int n = n0 + gc.wn*32 + nt*8 + 2*t;
            int h = n >> 6, hp = (n & 63) >> 1;
            int bb = m >> 11, l = m & (LL-1);
            Out[(((size_t)bb*HH + h)*LL + l)*32 + hp] = bf2(acc[mt][nt][0], acc[mt][nt][1]);
            int m2 = m + 8; bb = m2 >> 11; l = m2 & (LL-1);
            Out[(((size_t)bb*HH + h)*LL + l)*32 + hp] = bf2(acc[mt][nt][2], acc[mt][nt][3]);
        }
    }
}

// =================== output projection + bias + residual ===================
__global__ __launch_bounds__(256, 2) void outproj_mma_kernel(
    const float* __restrict__ qin, const float* __restrict__ bias)
{
    extern __shared__ unsigned dyn[];
    int m0 = blockIdx.x * 128, n0 = blockIdx.y * 64;
    GemmCore gc = gemm_init(g_AOh, g_Wob, m0, n0, dyn);

    float acc[2][4][4] = {};
    gemm_mainloop(gc, acc);

    int lane = threadIdx.x & 31, g = lane >> 2, t = lane & 3;
    #pragma unroll
    for (int mt = 0; mt < 2; mt++) {
        #pragma unroll
        for (int nt = 0; nt < 4; nt++) {
            int m = m0 + gc.wm*32 + mt*16 + g;
            int n = n0 + gc.wn*32 + nt*8 + 2*t;
            float2 bi = *(const float2*)&bias[n];
            {
                float2 rs = *(const float2*)&qin[(size_t)m*DD + n];
                *(float2*)&g_X[(size_t)m*DD + n] =
                    make_float2(acc[mt][nt][0] + bi.x + rs.x, acc[mt][nt][1] + bi.y + rs.y);
            }
            {
                int m2 = m + 8;
                float2 rs = *(const float2*)&qin[(size_t)m2*DD + n];
                *(float2*)&g_X[(size_t)m2*DD + n] =
                    make_float2(acc[mt][nt][2] + bi.x + rs.x, acc[mt][nt][3] + bi.y + rs.y);
            }
        }
    }
}

// =================== flash attention: bf16, 3-stage cp.async ring, occ 2 ===================
#define ATTN_SMEM ((128*32 + 3*2*64*32) * 4 + 3*64*4)

__global__ __launch_bounds__(256, 2) void attn_mma_kernel()
{
    extern __shared__ unsigned dyn[];
    unsigned* Qs = dyn;
    unsigned* KV = Qs + 128*32;
    float* mks   = (float*)(KV + 3*2*64*32);

    int tid = threadIdx.x, w = tid >> 5, lane = tid & 31;
    int g = lane >> 2, t = lane & 3;
    int bh = blockIdx.y;
    int b  = bh / HH, h = bh % HH;
    int q0 = blockIdx.x * 128;

    const unsigned* Qg = g_Qh + (size_t)bh * LL * 32;
    const unsigned* Kg = g_Kh + (size_t)bh * SS * 32;
    const unsigned* Vg = g_Vh + (size_t)bh * SS * 32;
    const float*    Mg = g_mkf + (size_t)b * SS;

    int r7 = lane & 7;
    unsigned QsB = saddr(Qs), KVB = saddr(KV), mkB = saddr(mks);

    int prow = tid >> 2;
    int pcb  = (tid & 3) * 2;
    unsigned kdstB = KVB + prow*128 + (((pcb    ) ^ (prow & 7)) << 4);
    unsigned kdstB2= KVB + prow*128 + (((pcb + 1) ^ (prow & 7)) << 4);

    auto prefetch = [&](int ti, int st) {
        int s0 = ti * 64;
        const uint4* kg = (const uint4*)(Kg + (size_t)(s0 + prow) * 32);
        const uint4* vg = (const uint4*)(Vg + (size_t)(s0 + prow) * 32);
        unsigned off = st * 16384;
        cpa16(kdstB  + off,        kg + pcb);
        cpa16(kdstB2 + off,        kg + pcb + 1);
        cpa16(kdstB  + off + 8192, vg + pcb);
        cpa16(kdstB2 + off + 8192, vg + pcb + 1);
        if (tid < 16) cpa16(mkB + st*256 + tid*16, Mg + s0 + tid*4);
        asm volatile("cp.async.commit_group;");
    };

    {
        int qrow = tid >> 1, qcb = (tid & 1) * 4;
        const uint4* src = (const uint4*)(Qg + (size_t)(q0 + qrow) * 32);
        #pragma unroll
        for (int i = 0; i < 4; i++) {
            int c = qcb + i;
            *(uint4*)(Qs + qrow*32 + ((c ^ (qrow & 7)) << 2)) = src[c];
        }
    }

    prefetch(0, 0);
    prefetch(1, 1);
    __syncthreads();

    unsigned qf[4][4];
    {
        int r = 16*w + r7 + 8*((lane >> 3) & 1);
        int cq = lane >> 4;
        #pragma unroll
        for (int kc = 0; kc < 4; kc++) {
            int ch = 2*kc + cq;
            ldsm4(qf[kc], QsB + r*128 + ((ch ^ r7) << 4));
        }
    }

    float o[8][4] = {};
    float mold0 = -1e30f, mold1 = -1e30f, l0 = 0.f, l1 = 0.f;

    int rK = r7,                       cK = lane >> 3;
    int rV = r7 + 8*((lane >> 3) & 1), cV = lane >> 4;

    const int NT = SS / 64;
    for (int it = 0; it < NT; it++) {
        int st = it % 3;
        if (it + 1 < NT) asm volatile("cp.async.wait_group 1;");
        else             asm volatile("cp.async.wait_group 0;");
        __syncthreads();
        if (it + 2 < NT) prefetch(it + 2, (it + 2) % 3);

        unsigned KsB = KVB + st*16384;
        unsigned VsB = KsB + 8192;
        const float* mkp = mks + st*64;

        float sc[8][4] = {};
        #pragma unroll
        for (int jp = 0; jp < 2; jp++) {
            #pragma unroll
            for (int nt = 0; nt < 8; nt++) {
                unsigned kb[4];
                int r = nt*8 + rK, ch = 4*jp + cK;
                ldsm4(kb, KsB + r*128 + ((ch ^ rK) << 4));
                mma16(sc[nt], qf[2*jp][0], qf[2*jp][1], qf[2*jp][2], qf[2*jp][3], kb[0], kb[1]);
                mma16(sc[nt], qf[2*jp+1][0], qf[2*jp+1][1], qf[2*jp+1][2], qf[2*jp+1][3], kb[2], kb[3]);
            }
        }

        float mx0 = -1e30f, mx1 = -1e30f;
        #pragma unroll
        for (int nt = 0; nt < 8; nt++) {
            float2 mv = *(const float2*)&mkp[nt*8 + 2*t];
            sc[nt][0] = sc[nt][0]*SCALE2 + mv.x;
            sc[nt][1] = sc[nt][1]*SCALE2 + mv.y;
            sc[nt][2] = sc[nt][2]*SCALE2 + mv.x;
            sc[nt][3] = sc[nt][3]*SCALE2 + mv.y;
            mx0 = fmaxf(mx0, fmaxf(sc[nt][0], sc[nt][1]));
            mx1 = fmaxf(mx1, fmaxf(sc[nt][2], sc[nt][3]));
        }
        mx0 = fmaxf(mx0, __shfl_xor_sync(0xffffffffu, mx0, 1));
        mx0 = fmaxf(mx0, __shfl_xor_sync(0xffffffffu, mx0, 2));
        mx1 = fmaxf(mx1, __shfl_xor_sync(0xffffffffu, mx1, 1));
        mx1 = fmaxf(mx1, __shfl_xor_sync(0xffffffffu, mx1, 2));

        float mn0 = fmaxf(mold0, mx0), mn1 = fmaxf(mold1, mx1);
        float corr0 = exp2f(mold0 - mn0), corr1 = exp2f(mold1 - mn1);
        mold0 = mn0; mold1 = mn1;

        float sum0 = 0.f, sum1 = 0.f;
        #pragma unroll
        for (int nt = 0; nt < 8; nt++) {
            sc[nt][0] = exp2f(sc[nt][0] - mn0);
            sc[nt][1] = exp2f(sc[nt][1] - mn0);
            sc[nt][2] = exp2f(sc[nt][2] - mn1);
            sc[nt][3] = exp2f(sc[nt][3] - mn1);
            sum0 += sc[nt][0] + sc[nt][1];
            sum1 += sc[nt][2] + sc[nt][3];
        }
        sum0 += __shfl_xor_sync(0xffffffffu, sum0, 1);
        sum0 += __shfl_xor_sync(0xffffffffu, sum0, 2);
        sum1 += __shfl_xor_sync(0xffffffffu, sum1, 1);
        sum1 += __shfl_xor_sync(0xffffffffu, sum1, 2);
        l0 = l0*corr0 + sum0;
        l1 = l1*corr1 + sum1;
        #pragma unroll
        for (int nt = 0; nt < 8; nt++) {
            o[nt][0] *= corr0; o[nt][1] *= corr0;
            o[nt][2] *= corr1; o[nt][3] *= corr1;
        }

        #pragma unroll
        for (int j = 0; j < 4; j++) {
            unsigned a0 = bf2(sc[2*j][0],   sc[2*j][1]);
            unsigned a1 = bf2(sc[2*j][2],   sc[2*j][3]);
            unsigned a2 = bf2(sc[2*j+1][0], sc[2*j+1][1]);
            unsigned a3 = bf2(sc[2*j+1][2], sc[2*j+1][3]);
            #pragma unroll
            for (int np = 0; np < 4; np++) {
                unsigned vb[4];
                int r = 16*j + rV, ch = 2*np + cV;
                ldsm4t(vb, VsB + r*128 + ((ch ^ r7) << 4));
                mma16(o[2*np],   a0, a1, a2, a3, vb[0], vb[1]);
                mma16(o[2*np+1], a0, a1, a2, a3, vb[2], vb[3]);
            }
        }
    }

    float inv0 = 1.0f / l0, inv1 = 1.0f / l1;
    int row0 = q0 + w*16 + g;
    unsigned* d0 = g_AOh + ((size_t)b*LL + row0)*384 + h*32;
    unsigned* d1 = d0 + (size_t)8*384;
    #pragma unroll
    for (int nt = 0; nt < 8; nt++) {
        d0[nt*4 + t] = bf2(o[nt][0]*inv0, o[nt][1]*inv0);
        d1[nt*4 + t] = bf2(o[nt][2]*inv1, o[nt][3]*inv1);
    }
}

// =================== LayerNorm ===================
__global__ __launch_bounds__(256) void ln_kernel(
    const float* __restrict__ gamma, const float* __restrict__ beta,
    float* __restrict__ out)
{
    __shared__ float sh[18];
    int row = blockIdx.x, tid = threadIdx.x;
    const float* x = g_X + (size_t)row * DD;
    float v0 = x[tid], v1 = x[tid+256], v2 = x[tid+512];
    float s  = v0 + v1 + v2;
    float sq = v0*v0 + v1*v1 + v2*v2;
    #pragma unroll
    for (int off = 16; off > 0; off >>= 1) {
        s  += __shfl_xor_sync(0xffffffffu, s,  off);
        sq += __shfl_xor_sync(0xffffffffu, sq, off);
    }
    int wid = tid >> 5;
    if ((tid & 31) == 0) { sh[wid] = s; sh[wid + 8] = sq; }
    __syncthreads();
    if (tid == 0) {
        float S = 0.f, Q2 = 0.f;
        #pragma unroll
        for (int i = 0; i < 8; i++) { S += sh[i]; Q2 += sh[i+8]; }
        float mu  = S  * (1.0f / 768.0f);
        float var = Q2 * (1.0f / 768.0f) - mu * mu;
        sh[16] = mu;
        sh[17] = rsqrtf(var + 1e-5f);
    }
    __syncthreads();
    float mu = sh[16], rstd = sh[17];
    float* o = out + (size_t)row * DD;
    o[tid]     = (v0 - mu) * rstd * gamma[tid]     + beta[tid];
    o[tid+256] = (v1 - mu) * rstd * gamma[tid+256] + beta[tid+256];
    o[tid+512] = (v2 - mu) * rstd * gamma[tid+512] + beta[tid+512];
}

// =================== launch ===================
extern "C" void kernel_launch(void* const* d_in, const int* in_sizes, int n_in,
                              void* d_out, int out_size)
{
    const float* q     = (const float*)d_in[0];
    const float* k     = (const float*)d_in[1];
    const float* v     = (const float*)d_in[2];
    const int*   mask  = (const int*)  d_in[3];
    const float* Wq    = (const float*)d_in[4];
    const float* Wk    = (const float*)d_in[5];
    const float* Wv    = (const float*)d_in[6];
    const float* W     = (const float*)d_in[7];
    const float* bias  = (const float*)d_in[8];
    const float* gamma = (const float*)d_in[9];
    const float* beta  = (const float*)d_in[10];
    float* out = (float*)d_out;

    cudaFuncSetAttribute(attn_mma_kernel,    cudaFuncAttributeMaxDynamicSharedMemorySize, ATTN_SMEM);
    cudaFuncSetAttribute(qkv_mma_kernel,     cudaFuncAttributeMaxDynamicSharedMemorySize, GEMM_SMEM);
    cudaFuncSetAttribute(outproj_mma_kernel, cudaFuncAttributeMaxDynamicSharedMemorySize, GEMM_SMEM);

    const int ACT_BLK = MTOT*DD/4/256;   // 3072
    const int W_BLK   = DD*DD/4/256;     // 576
    cvt_kernel<<<ACT_BLK, 256>>>(q,  0);
    cvt_kernel<<<ACT_BLK, 256>>>(k,  1);
    cvt_kernel<<<ACT_BLK, 256>>>(v,  2);
    cvt_kernel<<<W_BLK,   256>>>(Wq, 3);
    cvt_kernel<<<W_BLK,   256>>>(Wk, 4);
    cvt_kernel<<<W_BLK,   256>>>(Wv, 5);
    cvt_kernel<<<W_BLK,   256>>>(W,  6);
    maskf_kernel<<<BB*SS/256, 256>>>(mask);

    qkv_mma_kernel    <<<dim3(MTOT/128, DD/64, 3), 256, GEMM_SMEM>>>();
    attn_mma_kernel   <<<dim3(LL/128, BB*HH), 256, ATTN_SMEM>>>();
    outproj_mma_kernel<<<dim3(MTOT/128, DD/64), 256, GEMM_SMEM>>>(q, bias);
    ln_kernel         <<<MTOT, 256>>>(gamma, beta, out);
}

// round 16
// speedup vs baseline: 4.8337x; 1.1512x over previous
#include <cuda_runtime.h>
#include <math.h>

#define BB   2
#define LL   2048
#define SS   2048
#define DD   768
#define HH   12
#define HDIM 64
#define MTOT (BB*LL)   // 4096
#define LOG2E 1.4426950408889634f
#define SCALE2 (0.125f * LOG2E)

// ---------------- scratch (no allocations allowed) ----------------
__device__ unsigned g_Qh [(size_t)BB*HH*LL*HDIM/2];   // bf16x2 (b,h,l,hd/2)
__device__ unsigned g_Kh [(size_t)BB*HH*SS*HDIM/2];
__device__ unsigned g_Vh [(size_t)BB*HH*SS*HDIM/2];
__device__ unsigned g_AOh[(size_t)MTOT*DD/2];         // attention out bf16, (b,l,d/2)
__device__ float    g_X  [(size_t)MTOT*DD];           // pre-LN residual fp32
__device__ float    g_mkf[(size_t)BB*SS];             // additive mask * log2e
// bf16 copies of inputs/weights
__device__ unsigned g_qb [(size_t)MTOT*DD/2];
__device__ unsigned g_kb [(size_t)MTOT*DD/2];
__device__ unsigned g_vb [(size_t)MTOT*DD/2];
__device__ unsigned g_Wqb[(size_t)DD*DD/2];
__device__ unsigned g_Wkb[(size_t)DD*DD/2];
__device__ unsigned g_Wvb[(size_t)DD*DD/2];
__device__ unsigned g_Wob[(size_t)DD*DD/2];

// ---------------- helpers ----------------
__device__ __forceinline__ unsigned bf2(float lo, float hi) {
    unsigned r; asm("cvt.rn.bf16x2.f32 %0, %1, %2;" : "=r"(r) : "f"(hi), "f"(lo));
    return r;
}
__device__ __forceinline__ void mma16(float* c, unsigned a0, unsigned a1, unsigned a2, unsigned a3,
                                      unsigned b0, unsigned b1) {
    asm volatile(
        "mma.sync.aligned.m16n8k16.row.col.f32.bf16.bf16.f32 "
        "{%0,%1,%2,%3},{%4,%5,%6,%7},{%8,%9},{%0,%1,%2,%3};"
        : "+f"(c[0]), "+f"(c[1]), "+f"(c[2]), "+f"(c[3])
        : "r"(a0), "r"(a1), "r"(a2), "r"(a3), "r"(b0), "r"(b1));
}
__device__ __forceinline__ void ldsm4(unsigned* r, unsigned a) {
    asm volatile("ldmatrix.sync.aligned.m8n8.x4.shared.b16 {%0,%1,%2,%3}, [%4];"
        : "=r"(r[0]), "=r"(r[1]), "=r"(r[2]), "=r"(r[3]) : "r"(a));
}
__device__ __forceinline__ void ldsm4t(unsigned* r, unsigned a) {
    asm volatile("ldmatrix.sync.aligned.m8n8.x4.trans.shared.b16 {%0,%1,%2,%3}, [%4];"
        : "=r"(r[0]), "=r"(r[1]), "=r"(r[2]), "=r"(r[3]) : "r"(a));
}
__device__ __forceinline__ unsigned saddr(const void* p) {
    return (unsigned)__cvta_generic_to_shared(p);
}
__device__ __forceinline__ void cpa16(unsigned sdst, const void* gsrc) {
    asm volatile("cp.async.cg.shared.global [%0], [%1], 16;" :: "r"(sdst), "l"(gsrc));
}

// =================== single fused preprocess kernel ===================
// regions: 3 activations (fp32->bf16), 4 weights (fp32->bf16), mask (int->float*log2e)
#define ACT4 ((size_t)MTOT*DD/4)   // 786432 float4s per activation
#define WT4  ((size_t)DD*DD/4)     // 147456 float4s per weight
#define MK4  ((size_t)BB*SS/4)     // 1024 int4s
#define PREP_BLOCKS ((3*ACT4 + 4*WT4 + MK4 + 255)/256)

__global__ __launch_bounds__(256) void prep_kernel(
    const float* __restrict__ q, const float* __restrict__ k, const float* __restrict__ v,
    const float* __restrict__ Wq, const float* __restrict__ Wk, const float* __restrict__ Wv,
    const float* __restrict__ W, const int* __restrict__ mask)
{
    size_t gi = (size_t)blockIdx.x * 256 + threadIdx.x;
    if (gi < 3*ACT4) {
        int which = (int)(gi / ACT4); size_t i = gi - (size_t)which*ACT4;
        const float* src = (which == 0) ? q : (which == 1) ? k : v;
        unsigned* dst    = (which == 0) ? g_qb : (which == 1) ? g_kb : g_vb;
        float4 vv = ((const float4*)src)[i];
        ((uint2*)dst)[i] = make_uint2(bf2(vv.x, vv.y), bf2(vv.z, vv.w));
    } else if (gi < 3*ACT4 + 4*WT4) {
        size_t r = gi - 3*ACT4;
        int which = (int)(r / WT4); size_t i = r - (size_t)which*WT4;
        const float* src = (which == 0) ? Wq : (which == 1) ? Wk : (which == 2) ? Wv : W;
        unsigned* dst    = (which == 0) ? g_Wqb : (which == 1) ? g_Wkb : (which == 2) ? g_Wvb : g_Wob;
        float4 vv = ((const float4*)src)[i];
        ((uint2*)dst)[i] = make_uint2(bf2(vv.x, vv.y), bf2(vv.z, vv.w));
    } else {
        size_t i = gi - 3*ACT4 - 4*WT4;
        if (i < MK4) {
            int4 m = ((const int4*)mask)[i];
            const float c = -1000000.0f * LOG2E;
            ((float4*)g_mkf)[i] = make_float4((1.0f-(float)m.x)*c, (1.0f-(float)m.y)*c,
                                              (1.0f-(float)m.z)*c, (1.0f-(float)m.w)*c);
        }
    }
}

// =================== shared GEMM core: 3-stage cp.async, BM=128 BN=64 BK=64 ===================
#define GEMM_SMEM (3*(128*32 + 64*32)*4)

struct GemmCore {
    unsigned AsB0, BsB0;
    int lrA, cbA, lrB, cbB;
    const uint4 *agbase, *bgbase;
    int r7, rA, cA, rB, cB;
    int wm, wn;
};

__device__ __forceinline__ GemmCore gemm_init(const unsigned* Ab, const unsigned* Bb,
                                              int m0, int n0, unsigned* dyn) {
    GemmCore gc;
    int tid = threadIdx.x, lane = tid & 31;
    gc.lrA = tid >> 1; gc.cbA = (tid & 1) * 4;
    gc.lrB = tid >> 2; gc.cbB = (tid & 3) * 2;
    gc.agbase = (const uint4*)(Ab + (size_t)(m0 + gc.lrA) * (DD/2));
    gc.bgbase = (const uint4*)(Bb + (size_t)(n0 + gc.lrB) * (DD/2));
    gc.r7 = lane & 7;
    gc.rA = gc.r7 + 8*((lane >> 3) & 1); gc.cA = lane >> 4;
    gc.rB = gc.r7;                       gc.cB = lane >> 3;
    int w = tid >> 5;
    gc.wm = w & 3; gc.wn = w >> 2;
    gc.AsB0 = saddr(dyn);
    gc.BsB0 = saddr(dyn + 3*128*32);
    return gc;
}

__device__ __forceinline__ void gemm_prefetch(const GemmCore& gc, int ti, int st) {
    unsigned offA = gc.AsB0 + st*16384 + gc.lrA*128;
    const uint4* ag = gc.agbase + ti*8;
    #pragma unroll
    for (int i = 0; i < 4; i++) {
        int c = gc.cbA + i;
        cpa16(offA + ((c ^ (gc.lrA & 7)) << 4), ag + c);
    }
    unsigned offB = gc.BsB0 + st*8192 + gc.lrB*128;
    const uint4* bg = gc.bgbase + ti*8;
    #pragma unroll
    for (int i = 0; i < 2; i++) {
        int c = gc.cbB + i;
        cpa16(offB + ((c ^ (gc.lrB & 7)) << 4), bg + c);
    }
    asm volatile("cp.async.commit_group;");
}

__device__ __forceinline__ void gemm_mainloop(const GemmCore& gc, float acc[2][4][4]) {
    const int NT = DD / 64;   // 12
    gemm_prefetch(gc, 0, 0);
    gemm_prefetch(gc, 1, 1);
    for (int it = 0; it < NT; it++) {
        int st = it % 3;
        if (it + 1 < NT) asm volatile("cp.async.wait_group 1;");
        else             asm volatile("cp.async.wait_group 0;");
        __syncthreads();
        if (it + 2 < NT) gemm_prefetch(gc, it + 2, (it + 2) % 3);

        unsigned AsB = gc.AsB0 + st*16384;
        unsigned BsB = gc.BsB0 + st*8192;
        #pragma unroll
        for (int jp = 0; jp < 2; jp++) {
            unsigned af[2][2][4];
            #pragma unroll
            for (int mt = 0; mt < 2; mt++)
                #pragma unroll
                for (int kk = 0; kk < 2; kk++) {
                    int r = gc.wm*32 + mt*16 + gc.rA;
                    int ch = 2*(2*jp + kk) + gc.cA;
                    ldsm4(af[mt][kk], AsB + r*128 + ((ch ^ gc.r7) << 4));
                }
            unsigned bf[4][4];
            #pragma unroll
            for (int nt = 0; nt < 4; nt++) {
                int r = gc.wn*32 + nt*8 + gc.rB;
                int ch = 4*jp + gc.cB;
                ldsm4(bf[nt], BsB + r*128 + ((ch ^ gc.r7) << 4));
            }
            #pragma unroll
            for (int mt = 0; mt < 2; mt++)
                #pragma unroll
                for (int nt = 0; nt < 4; nt++) {
                    mma16(acc[mt][nt], af[mt][0][0], af[mt][0][1], af[mt][0][2], af[mt][0][3],
                          bf[nt][0], bf[nt][1]);
                    mma16(acc[mt][nt], af[mt][1][0], af[mt][1][1], af[mt][1][2], af[mt][1][3],
                          bf[nt][2], bf[nt][3]);
                }
        }
        __syncthreads();
    }
}

// =================== QKV projection ===================
__global__ __launch_bounds__(256, 2) void qkv_mma_kernel()
{
    extern __shared__ unsigned dyn[];
    int which = blockIdx.z;
    const unsigned* Ab = (which == 0) ? g_qb  : (which == 1) ? g_kb  : g_vb;
    const unsigned* Bb = (which == 0) ? g_Wqb : (which == 1) ? g_Wkb : g_Wvb;
    unsigned* Out      = (which == 0) ? g_Qh  : (which == 1) ? g_Kh  : g_Vh;

    int m0 = blockIdx.x * 128, n0 = blockIdx.y * 64;
    GemmCore gc = gemm_init(Ab, Bb, m0, n0, dyn);

    float acc[2][4][4] = {};
    gemm_mainloop(gc, acc);

    int lane = threadIdx.x & 31, g = lane >> 2, t = lane & 3;
    #pragma unroll
    for (int mt = 0; mt < 2; mt++) {
        #pragma unroll
        for (int nt = 0; nt < 4; nt++) {
            int m = m0 + gc.wm*32 + mt*16 + g;
            int n = n0 + gc.wn*32 + nt*8 + 2*t;
            int h = n >> 6, hp = (n & 63) >> 1;
            int bb = m >> 11, l = m & (LL-1);
            Out[(((size_t)bb*HH + h)*LL + l)*32 + hp] = bf2(acc[mt][nt][0], acc[mt][nt][1]);
            int m2 = m + 8; bb = m2 >> 11; l = m2 & (LL-1);
            Out[(((size_t)bb*HH + h)*LL + l)*32 + hp] = bf2(acc[mt][nt][2], acc[mt][nt][3]);
        }
    }
}

// =================== output projection + bias + residual ===================
__global__ __launch_bounds__(256, 2) void outproj_mma_kernel(
    const float* __restrict__ qin, const float* __restrict__ bias)
{
    extern __shared__ unsigned dyn[];
    int m0 = blockIdx.x * 128, n0 = blockIdx.y * 64;
    GemmCore gc = gemm_init(g_AOh, g_Wob, m0, n0, dyn);

    float acc[2][4][4] = {};
    gemm_mainloop(gc, acc);

    int lane = threadIdx.x & 31, g = lane >> 2, t = lane & 3;
    #pragma unroll
    for (int mt = 0; mt < 2; mt++) {
        #pragma unroll
        for (int nt = 0; nt < 4; nt++) {
            int m = m0 + gc.wm*32 + mt*16 + g;
            int n = n0 + gc.wn*32 + nt*8 + 2*t;
            float2 bi = *(const float2*)&bias[n];
            {
                float2 rs = *(const float2*)&qin[(size_t)m*DD + n];
                *(float2*)&g_X[(size_t)m*DD + n] =
                    make_float2(acc[mt][nt][0] + bi.x + rs.x, acc[mt][nt][1] + bi.y + rs.y);
            }
            {
                int m2 = m + 8;
                float2 rs = *(const float2*)&qin[(size_t)m2*DD + n];
                *(float2*)&g_X[(size_t)m2*DD + n] =
                    make_float2(acc[mt][nt][2] + bi.x + rs.x, acc[mt][nt][3] + bi.y + rs.y);
            }
        }
    }
}

// =================== flash attention: no-max softmax (statically safe), lane-local sums ===================
#define ATTN_SMEM ((128*32 + 3*2*64*32) * 4 + 3*64*4)

__global__ __launch_bounds__(256, 2) void attn_mma_kernel()
{
    extern __shared__ unsigned dyn[];
    unsigned* Qs = dyn;
    unsigned* KV = Qs + 128*32;
    float* mks   = (float*)(KV + 3*2*64*32);

    int tid = threadIdx.x, w = tid >> 5, lane = tid & 31;
    int g = lane >> 2, t = lane & 3;
    int bh = blockIdx.y;
    int b  = bh / HH, h = bh % HH;
    int q0 = blockIdx.x * 128;

    const unsigned* Qg = g_Qh + (size_t)bh * LL * 32;
    const unsigned* Kg = g_Kh + (size_t)bh * SS * 32;
    const unsigned* Vg = g_Vh + (size_t)bh * SS * 32;
    const float*    Mg = g_mkf + (size_t)b * SS;

    int r7 = lane & 7;
    unsigned QsB = saddr(Qs), KVB = saddr(KV), mkB = saddr(mks);

    int prow = tid >> 2;
    int pcb  = (tid & 3) * 2;
    unsigned kdstB = KVB + prow*128 + (((pcb    ) ^ (prow & 7)) << 4);
    unsigned kdstB2= KVB + prow*128 + (((pcb + 1) ^ (prow & 7)) << 4);

    auto prefetch = [&](int ti, int st) {
        int s0 = ti * 64;
        const uint4* kg = (const uint4*)(Kg + (size_t)(s0 + prow) * 32);
        const uint4* vg = (const uint4*)(Vg + (size_t)(s0 + prow) * 32);
        unsigned off = st * 16384;
        cpa16(kdstB  + off,        kg + pcb);
        cpa16(kdstB2 + off,        kg + pcb + 1);
        cpa16(kdstB  + off + 8192, vg + pcb);
        cpa16(kdstB2 + off + 8192, vg + pcb + 1);
        if (tid < 16) cpa16(mkB + st*256 + tid*16, Mg + s0 + tid*4);
        asm volatile("cp.async.commit_group;");
    };

    {
        int qrow = tid >> 1, qcb = (tid & 1) * 4;
        const uint4* src = (const uint4*)(Qg + (size_t)(q0 + qrow) * 32);
        #pragma unroll
        for (int i = 0; i < 4; i++) {
            int c = qcb + i;
            *(uint4*)(Qs + qrow*32 + ((c ^ (qrow & 7)) << 2)) = src[c];
        }
    }

    prefetch(0, 0);
    prefetch(1, 1);
    __syncthreads();

    unsigned qf[4][4];
    {
        int r = 16*w + r7 + 8*((lane >> 3) & 1);
        int cq = lane >> 4;
        #pragma unroll
        for (int kc = 0; kc < 4; kc++) {
            int ch = 2*kc + cq;
            ldsm4(qf[kc], QsB + r*128 + ((ch ^ r7) << 4));
        }
    }

    float o[8][4] = {};
    float l0 = 0.f, l1 = 0.f;   // lane-local partial row sums (no max tracking needed:
                                // |score*SCALE2| <= ~10 statically, exp2 cannot overflow;
                                // masked keys underflow to exactly 0)

    int rK = r7,                       cK = lane >> 3;
    int rV = r7 + 8*((lane >> 3) & 1), cV = lane >> 4;

    const int NT = SS / 64;
    for (int it = 0; it < NT; it++) {
        int st = it % 3;
        if (it + 1 < NT) asm volatile("cp.async.wait_group 1;");
        else             asm volatile("cp.async.wait_group 0;");
        __syncthreads();
        if (it + 2 < NT) prefetch(it + 2, (it + 2) % 3);

        unsigned KsB = KVB + st*16384;
        unsigned VsB = KsB + 8192;
        const float* mkp = mks + st*64;

        float sc[8][4] = {};
        #pragma unroll
        for (int jp = 0; jp < 2; jp++) {
            #pragma unroll
            for (int nt = 0; nt < 8; nt++) {
                unsigned kb[4];
                int r = nt*8 + rK, ch = 4*jp + cK;
                ldsm4(kb, KsB + r*128 + ((ch ^ rK) << 4));
                mma16(sc[nt], qf[2*jp][0], qf[2*jp][1], qf[2*jp][2], qf[2*jp][3], kb[0], kb[1]);
                mma16(sc[nt], qf[2*jp+1][0], qf[2*jp+1][1], qf[2*jp+1][2], qf[2*jp+1][3], kb[2], kb[3]);
            }
        }

        // softmax numerator: p = exp2(score*SCALE2 + mask), no max subtraction
        #pragma unroll
        for (int nt = 0; nt < 8; nt++) {
            float2 mv = *(const float2*)&mkp[nt*8 + 2*t];
            sc[nt][0] = exp2f(sc[nt][0]*SCALE2 + mv.x);
            sc[nt][1] = exp2f(sc[nt][1]*SCALE2 + mv.y);
            sc[nt][2] = exp2f(sc[nt][2]*SCALE2 + mv.x);
            sc[nt][3] = exp2f(sc[nt][3]*SCALE2 + mv.y);
            l0 += sc[nt][0] + sc[nt][1];
            l1 += sc[nt][2] + sc[nt][3];
        }

        // O += P V ; P packed straight from sc registers
        #pragma unroll
        for (int j = 0; j < 4; j++) {
            unsigned a0 = bf2(sc[2*j][0],   sc[2*j][1]);
            unsigned a1 = bf2(sc[2*j][2],   sc[2*j][3]);
            unsigned a2 = bf2(sc[2*j+1][0], sc[2*j+1][1]);
            unsigned a3 = bf2(sc[2*j+1][2], sc[2*j+1][3]);
            #pragma unroll
            for (int np = 0; np < 4; np++) {
                unsigned vb[4];
                int r = 16*j + rV, ch = 2*np + cV;
                ldsm4t(vb, VsB + r*128 + ((ch ^ r7) << 4));
                mma16(o[2*np],   a0, a1, a2, a3, vb[0], vb[1]);
                mma16(o[2*np+1], a0, a1, a2, a3, vb[2], vb[3]);
            }
        }
    }

    // single final reduction across the 4 lanes sharing each row
    l0 += __shfl_xor_sync(0xffffffffu, l0, 1);
    l0 += __shfl_xor_sync(0xffffffffu, l0, 2);
    l1 += __shfl_xor_sync(0xffffffffu, l1, 1);
    l1 += __shfl_xor_sync(0xffffffffu, l1, 2);

    float inv0 = 1.0f / l0, inv1 = 1.0f / l1;
    int row0 = q0 + w*16 + g;
    unsigned* d0 = g_AOh + ((size_t)b*LL + row0)*384 + h*32;
    unsigned* d1 = d0 + (size_t)8*384;
    #pragma unroll
    for (int nt = 0; nt < 8; nt++) {
        d0[nt*4 + t] = bf2(o[nt][0]*inv0, o[nt][1]*inv0);
        d1[nt*4 + t] = bf2(o[nt][2]*inv1, o[nt][3]*inv1);
    }
}

// =================== LayerNorm ===================
__global__ __launch_bounds__(256) void ln_kernel(
    const float* __restrict__ gamma, const float* __restrict__ beta,
    float* __restrict__ out)
{
    __shared__ float sh[18];
    int row = blockIdx.x, tid = threadIdx.x;
    const float* x = g_X + (size_t)row * DD;
    float v0 = x[tid], v1 = x[tid+256], v2 = x[tid+512];
    float s  = v0 + v1 + v2;
    float sq = v0*v0 + v1*v1 + v2*v2;
    #pragma unroll
    for (int off = 16; off > 0; off >>= 1) {
        s  += __shfl_xor_sync(0xffffffffu, s,  off);
        sq += __shfl_xor_sync(0xffffffffu, sq, off);
    }
    int wid = tid >> 5;
    if ((tid & 31) == 0) { sh[wid] = s; sh[wid + 8] = sq; }
    __syncthreads();
    if (tid == 0) {
        float S = 0.f, Q2 = 0.f;
        #pragma unroll
        for (int i = 0; i < 8; i++) { S += sh[i]; Q2 += sh[i+8]; }
        float mu  = S  * (1.0f / 768.0f);
        float var = Q2 * (1.0f / 768.0f) - mu * mu;
        sh[16] = mu;
        sh[17] = rsqrtf(var + 1e-5f);
    }
    __syncthreads();
    float mu = sh[16], rstd = sh[17];
    float* o = out + (size_t)row * DD;
    o[tid]     = (v0 - mu) * rstd * gamma[tid]     + beta[tid];
    o[tid+256] = (v1 - mu) * rstd * gamma[tid+256] + beta[tid+256];
    o[tid+512] = (v2 - mu) * rstd * gamma[tid+512] + beta[tid+512];
}

// =================== launch ===================
extern "C" void kernel_launch(void* const* d_in, const int* in_sizes, int n_in,
                              void* d_out, int out_size)
{
    const float* q     = (const float*)d_in[0];
    const float* k     = (const float*)d_in[1];
    const float* v     = (const float*)d_in[2];
    const int*   mask  = (const int*)  d_in[3];
    const float* Wq    = (const float*)d_in[4];
    const float* Wk    = (const float*)d_in[5];
    const float* Wv    = (const float*)d_in[6];
    const float* W     = (const float*)d_in[7];
    const float* bias  = (const float*)d_in[8];
    const float* gamma = (const float*)d_in[9];
    const float* beta  = (const float*)d_in[10];
    float* out = (float*)d_out;

    cudaFuncSetAttribute(attn_mma_kernel,    cudaFuncAttributeMaxDynamicSharedMemorySize, ATTN_SMEM);
    cudaFuncSetAttribute(qkv_mma_kernel,     cudaFuncAttributeMaxDynamicSharedMemorySize, GEMM_SMEM);
    cudaFuncSetAttribute(outproj_mma_kernel, cudaFuncAttributeMaxDynamicSharedMemorySize, GEMM_SMEM);

    prep_kernel       <<<(unsigned)PREP_BLOCKS, 256>>>(q, k, v, Wq, Wk, Wv, W, mask);
    qkv_mma_kernel    <<<dim3(MTOT/128, DD/64, 3), 256, GEMM_SMEM>>>();
    attn_mma_kernel   <<<dim3(LL/128, BB*HH), 256, ATTN_SMEM>>>();
    outproj_mma_kernel<<<dim3(MTOT/128, DD/64), 256, GEMM_SMEM>>>(q, bias);
    ln_kernel         <<<MTOT, 256>>>(gamma, beta, out);
}